// round 11
// baseline (speedup 1.0000x reference)
#include <cuda_runtime.h>
#include <cuda_fp16.h>
#include <math.h>
#include <stdint.h>

#define P 2048
#define D 1024
#define H 16
#define DH 64
#define HID 32
#define P3D 3072
#define LOG2E 1.44269504088896f

__device__ unsigned int g_q32[P * 512];        // [P][D/2] tau-packed, q*log2e/8
__device__ unsigned int g_k32[P * 512];        // [P][D/2] tau-packed
__device__ unsigned int g_v32[H * 64 * 1024];  // [H][64 d][1024 kvpair tau-slots]
__device__ unsigned int g_xp[P * 512];         // x tau-packed
__device__ unsigned int g_wqp[512 * P3D];      // w_qkv kpair-packed [D/2][3D]
__device__ unsigned int g_wph[512 * D];        // w_proj hi kpair-packed
__device__ unsigned int g_wpl[512 * D];
__device__ unsigned int g_ahi[P * 512];        // att tau-packed
__device__ unsigned int g_bias16[P * 1024];    // bias*log2e, half2-packed [P][P/2]

__device__ __forceinline__ int tau(int w) { return ((w & 3) << 1) | (w >> 2); }
__device__ __forceinline__ uint32_t h2pk(float a, float b) {
    __half2 h = __floats2half2_rn(a, b);
    return *reinterpret_cast<uint32_t*>(&h);
}
__device__ __forceinline__ float2 h2up(uint32_t u) {
    return __half22float2(*reinterpret_cast<__half2*>(&u));
}
__device__ __forceinline__ uint32_t smem_u32(const void* p) {
    uint32_t a;
    asm("{ .reg .u64 t; cvta.to.shared.u64 t, %1; cvt.u32.u64 %0, t; }" : "=r"(a) : "l"(p));
    return a;
}
__device__ __forceinline__ void mma16(float c[4], uint32_t a0, uint32_t a1,
                                      uint32_t a2, uint32_t a3,
                                      uint32_t b0, uint32_t b1) {
    asm volatile(
        "mma.sync.aligned.m16n8k16.row.col.f32.f16.f16.f32 "
        "{%0,%1,%2,%3},{%4,%5,%6,%7},{%8,%9},{%0,%1,%2,%3};\n"
        : "+f"(c[0]), "+f"(c[1]), "+f"(c[2]), "+f"(c[3])
        : "r"(a0), "r"(a1), "r"(a2), "r"(a3), "r"(b0), "r"(b1));
}
__device__ __forceinline__ void cp16(uint32_t dst, const void* src) {
    asm volatile("cp.async.ca.shared.global [%0], [%1], 16;" :: "r"(dst), "l"(src));
}
#define CP_COMMIT() asm volatile("cp.async.commit_group;" ::: "memory")
#define CP_WAIT0()  asm volatile("cp.async.wait_group 0;" ::: "memory")

// ---------------------------------------------------------------------------
// Single fused pack pre-pass
// ---------------------------------------------------------------------------
#define NPA (P * 512)
#define NPB (512 * P3D)
#define NPC (512 * D)

__global__ void pack_all(const float* __restrict__ x, const float* __restrict__ wq,
                         const float* __restrict__ wp,
                         unsigned int* __restrict__ xp, unsigned int* __restrict__ wqp,
                         unsigned int* __restrict__ wph, unsigned int* __restrict__ wpl) {
    int i = blockIdx.x * blockDim.x + threadIdx.x;
    if (i < NPA) {
        int row = i >> 9, p = i & 511;
        int slot = (p & ~7) | tau(p & 7);
        xp[((size_t)row << 9) + slot] =
            h2pk(x[(size_t)row * 1024 + 2 * p], x[(size_t)row * 1024 + 2 * p + 1]);
    } else if (i < NPA + NPB) {
        int j = i - NPA;
        int kp = j / P3D, n = j % P3D;
        wqp[j] = h2pk(wq[(size_t)(2 * kp) * P3D + n], wq[(size_t)(2 * kp + 1) * P3D + n]);
    } else {
        int j = i - NPA - NPB;
        int kp = j >> 10, n = j & 1023;
        float v0 = wp[(size_t)(2 * kp) * D + n], v1 = wp[(size_t)(2 * kp + 1) * D + n];
        __half h0 = __float2half_rn(v0), h1 = __float2half_rn(v1);
        wph[j] = h2pk(__half2float(h0), __half2float(h1));
        wpl[j] = h2pk(v0 - __half2float(h0), v1 - __half2float(h1));
    }
}

// ---------------------------------------------------------------------------
// Combo kernel, role INTERLEAVED by bx%19 (3 qkv : 16 rpb per group of 19)
// so both workloads co-reside on SMs from wave 1.
// ---------------------------------------------------------------------------
#define APu 24
#define BPu 136
#define QKV_SA (128 * APu)
#define QKV_SB (16 * BPu)
#define QKV_ST (QKV_SA + QKV_SB)
#define SM_QKV (2 * QKV_ST * 4)      // 41,984 B
#define NRPB_BLK 2048
#define HPt 24

__global__ __launch_bounds__(256, 2) void combo_qkv_rpb(
    const unsigned int* __restrict__ A0, const unsigned int* __restrict__ B0,
    unsigned int* __restrict__ Cq, unsigned int* __restrict__ Ck,
    __half* __restrict__ Cv,
    const float* __restrict__ rel,
    const float* __restrict__ w1, const float* __restrict__ b1,
    const float* __restrict__ w2, const float* __restrict__ b2,
    const float* __restrict__ w3, const float* __restrict__ b3,
    unsigned int* __restrict__ bias16) {
    extern __shared__ unsigned int smu[];
    const int tid = threadIdx.x, lane = tid & 31, warp = tid >> 5;
    const int r4 = lane >> 2, c4l = lane & 3;
    const int grp = blockIdx.x / 19, pos = blockIdx.x % 19;

    if (pos < 3) {
        // ------------------------- qkv GEMM body --------------------------
        const int qid = grp * 3 + pos;             // 0..383
        const uint32_t smb = smem_u32(smu);
        const int wm = warp >> 2, wn = warp & 3;
        const int n0 = (qid % 24) * 128, m0 = (qid / 24) * 128;
        const int Kp = 512;
        const int N = P3D;

        float acc[4][4][4];
        #pragma unroll
        for (int i = 0; i < 4; i++)
            #pragma unroll
            for (int j = 0; j < 4; j++)
                #pragma unroll
                for (int q = 0; q < 4; q++) acc[i][j][q] = 0.f;

        auto load_tile = [&](int kp0, int st) {
            const uint32_t sbase = smb + st * QKV_ST * 4;
            #pragma unroll
            for (int t = tid; t < 512; t += 256) {
                int ar = t >> 2, ac = (t & 3) * 4;
                cp16(sbase + (ar * APu + ac) * 4, &A0[(size_t)(m0 + ar) * Kp + kp0 + ac]);
            }
            #pragma unroll
            for (int t = tid; t < 512; t += 256) {
                int br = t >> 5, bc = (t & 31) * 4;
                cp16(sbase + (QKV_SA + br * BPu + bc) * 4,
                     &B0[(size_t)(kp0 + br) * N + n0 + bc]);
            }
            CP_COMMIT();
        };

        load_tile(0, 0);
        for (int it = 0; it < 32; it++) {
            const int st = it & 1;
            CP_WAIT0();
            __syncthreads();
            if (it + 1 < 32) load_tile((it + 1) * 16, st ^ 1);

            const unsigned int* Ah = smu + st * QKV_ST;
            const unsigned int* Bh = smu + st * QKV_ST + QKV_SA;
            #pragma unroll
            for (int ks = 0; ks < 2; ks++) {
                uint32_t ra[4][4], rb[4][2];
                #pragma unroll
                for (int mt = 0; mt < 4; mt++) {
                    const unsigned int* ap =
                        Ah + (wm * 64 + mt * 16 + r4) * APu + 8 * ks + 2 * c4l;
                    uint2 x0 = *(const uint2*)ap;
                    uint2 x1 = *(const uint2*)(ap + 8 * APu);
                    ra[mt][0] = x0.x; ra[mt][1] = x1.x; ra[mt][2] = x0.y; ra[mt][3] = x1.y;
                }
                #pragma unroll
                for (int nt = 0; nt < 4; nt++) {
                    int cn = wn * 32 + nt * 8 + r4;
                    rb[nt][0] = Bh[(8 * ks + c4l) * BPu + cn];
                    rb[nt][1] = Bh[(8 * ks + c4l + 4) * BPu + cn];
                }
                #pragma unroll
                for (int mt = 0; mt < 4; mt++)
                    #pragma unroll
                    for (int nt = 0; nt < 4; nt++)
                        mma16(acc[mt][nt], ra[mt][0], ra[mt][1], ra[mt][2], ra[mt][3],
                              rb[nt][0], rb[nt][1]);
            }
        }

        #pragma unroll
        for (int mt = 0; mt < 4; mt++)
            #pragma unroll
            for (int nt = 0; nt < 4; nt++) {
                int row = m0 + wm * 64 + mt * 16 + r4;
                int col = n0 + wn * 32 + nt * 8 + 2 * c4l;
                float v0 = acc[mt][nt][0], v1 = acc[mt][nt][1];
                float v2 = acc[mt][nt][2], v3 = acc[mt][nt][3];
                if (col < 2 * D) {           // Q,K -> tau-packed half2
                    const float sc = (col < D) ? (0.125f * LOG2E) : 1.0f;
                    const int dd = col & 1023;
                    const int hh = dd >> 6, dh = dd & 63;
                    const int pr = dh >> 1;
                    const int slot = hh * 32 + ((pr & ~7) | tau(pr & 7));
                    unsigned int* dst = (col < D) ? Cq : Ck;
                    dst[(size_t)row * 512 + slot]       = h2pk(v0 * sc, v1 * sc);
                    dst[(size_t)(row + 8) * 512 + slot] = h2pk(v2 * sc, v3 * sc);
                } else {                     // V -> transposed [h][d][kvslot]
                    const int dd = col - 2 * D;
                    const int hh = dd >> 6, dh = dd & 63;
                    const int kp = row >> 1, par = row & 1;
                    const int slot  = (kp & ~7) | tau(kp & 7);
                    const int slot8 = (kp & ~7) | tau((kp & 7) + 4);
                    __half* vb  = Cv + (((size_t)(hh * 64 + dh) << 10) + slot) * 2 + par;
                    __half* vb8 = Cv + (((size_t)(hh * 64 + dh) << 10) + slot8) * 2 + par;
                    vb[0]     = __float2half_rn(v0);
                    vb[2048]  = __float2half_rn(v1);
                    vb8[0]    = __float2half_rn(v2);
                    vb8[2048] = __float2half_rn(v3);
                }
            }
    } else {
        // --------------------------- RPB body ------------------------------
        __shared__ unsigned int h1s[8][16][HPt];
        const int rid = grp * 16 + (pos - 3);      // 0..2047

        uint32_t w1b0[4];
        float b1c[4][2], b2c[4][2], w3c[4][2];
        uint32_t w2f[2][4][2];
        #pragma unroll
        for (int nt = 0; nt < 4; nt++) {
            const int n = nt * 8 + r4;
            w1b0[nt] = (c4l == 0) ? h2pk(w1[n], w1[HID + n]) : 0u;
            const int cc = nt * 8 + 2 * c4l;
            b1c[nt][0] = b1[cc]; b1c[nt][1] = b1[cc + 1];
            b2c[nt][0] = b2[cc]; b2c[nt][1] = b2[cc + 1];
            w3c[nt][0] = w3[cc]; w3c[nt][1] = w3[cc + 1];
            #pragma unroll
            for (int ks = 0; ks < 2; ks++) {
                w2f[ks][nt][0] = h2pk(w2[(16 * ks + 2 * c4l) * HID + n],
                                      w2[(16 * ks + 2 * c4l + 1) * HID + n]);
                w2f[ks][nt][1] = h2pk(w2[(16 * ks + 2 * c4l + 8) * HID + n],
                                      w2[(16 * ks + 2 * c4l + 9) * HID + n]);
            }
        }
        const float b3v = b3[0];

        unsigned int (*h1)[HPt] = h1s[warp];
        const int gw = rid * 8 + warp;
        const int nW = NRPB_BLK * 8;
        for (int task = gw; task < (P * P) / 16; task += nW) {
            const int base = task * 16;
            const float2 ra = *(const float2*)&rel[(size_t)(base + r4) * 2];
            const float2 rb = *(const float2*)&rel[(size_t)(base + 8 + r4) * 2];
            const uint32_t a0 = (c4l == 0) ? h2pk(ra.x, ra.y) : 0u;
            const uint32_t a1 = (c4l == 0) ? h2pk(rb.x, rb.y) : 0u;

            float c1[4][4];
            #pragma unroll
            for (int nt = 0; nt < 4; nt++) {
                c1[nt][0] = b1c[nt][0]; c1[nt][1] = b1c[nt][1];
                c1[nt][2] = b1c[nt][0]; c1[nt][3] = b1c[nt][1];
                mma16(c1[nt], a0, a1, 0u, 0u, w1b0[nt], 0u);
            }
            #pragma unroll
            for (int g = 0; g < 2; g++) {
                uint2 w0 = make_uint2(
                    h2pk(fmaxf(c1[2*g][0], 0.f),   fmaxf(c1[2*g][1], 0.f)),
                    h2pk(fmaxf(c1[2*g+1][0], 0.f), fmaxf(c1[2*g+1][1], 0.f)));
                uint2 w1v = make_uint2(
                    h2pk(fmaxf(c1[2*g][2], 0.f),   fmaxf(c1[2*g][3], 0.f)),
                    h2pk(fmaxf(c1[2*g+1][2], 0.f), fmaxf(c1[2*g+1][3], 0.f)));
                *(uint2*)&h1[r4][8 * g + 2 * c4l]     = w0;
                *(uint2*)&h1[r4 + 8][8 * g + 2 * c4l] = w1v;
            }
            __syncwarp();
            float c2[4][4];
            #pragma unroll
            for (int nt = 0; nt < 4; nt++) {
                c2[nt][0] = b2c[nt][0]; c2[nt][1] = b2c[nt][1];
                c2[nt][2] = b2c[nt][0]; c2[nt][3] = b2c[nt][1];
            }
            #pragma unroll
            for (int ks = 0; ks < 2; ks++) {
                uint2 x0 = *(const uint2*)&h1[r4][8 * ks + 2 * c4l];
                uint2 x1 = *(const uint2*)&h1[r4 + 8][8 * ks + 2 * c4l];
                #pragma unroll
                for (int nt = 0; nt < 4; nt++)
                    mma16(c2[nt], x0.x, x1.x, x0.y, x1.y, w2f[ks][nt][0], w2f[ks][nt][1]);
            }
            float o0 = 0.f, o1 = 0.f;
            #pragma unroll
            for (int nt = 0; nt < 4; nt++) {
                o0 += fmaxf(c2[nt][0], 0.f) * w3c[nt][0] + fmaxf(c2[nt][1], 0.f) * w3c[nt][1];
                o1 += fmaxf(c2[nt][2], 0.f) * w3c[nt][0] + fmaxf(c2[nt][3], 0.f) * w3c[nt][1];
            }
            o0 += __shfl_xor_sync(0xffffffffu, o0, 1);
            o0 += __shfl_xor_sync(0xffffffffu, o0, 2);
            o1 += __shfl_xor_sync(0xffffffffu, o1, 1);
            o1 += __shfl_xor_sync(0xffffffffu, o1, 2);
            // pack adjacent bias cols (r4, r4+1) into half2 via shfl
            float o0n = __shfl_down_sync(0xffffffffu, o0, 4);
            float o1n = __shfl_down_sync(0xffffffffu, o1, 4);
            if (c4l == 0 && !(r4 & 1)) {
                const int pb = base >> 1;
                bias16[pb + (r4 >> 1)]     = h2pk((o0 + b3v) * LOG2E, (o0n + b3v) * LOG2E);
                bias16[pb + 4 + (r4 >> 1)] = h2pk((o1 + b3v) * LOG2E, (o1n + b3v) * LOG2E);
            }
            __syncwarp();
        }
    }
}

// ---------------------------------------------------------------------------
// fp16 proj GEMM (B hi/lo split, 2 MMAs), occupancy 3.
// ---------------------------------------------------------------------------
__global__ __launch_bounds__(128, 3) void gemm_proj(
    const unsigned int* __restrict__ A0,
    const unsigned int* __restrict__ B0, const unsigned int* __restrict__ B1,
    float* __restrict__ C, int M, int N, int K) {
    constexpr int SA = 64 * APu;
    constexpr int SB = 16 * BPu;
    constexpr int BLO = SA + SB;
    constexpr int ST  = SA + 2 * SB;
    extern __shared__ unsigned int smu[];
    const uint32_t smb = smem_u32(smu);

    const int tid = threadIdx.x, lane = tid & 31, warp = tid >> 5;
    const int wn = warp & 3;
    const int m0 = blockIdx.y * 64, n0 = blockIdx.x * 128;
    const int r4 = lane >> 2, c4l = lane & 3;
    const int Kp = K / 2;

    float acc[4][4][4];
    #pragma unroll
    for (int i = 0; i < 4; i++)
        #pragma unroll
        for (int j = 0; j < 4; j++)
            #pragma unroll
            for (int q = 0; q < 4; q++) acc[i][j][q] = 0.f;

    auto load_tile = [&](int kp0, int st) {
        const uint32_t sbase = smb + st * ST * 4;
        #pragma unroll
        for (int t = tid; t < 256; t += 128) {
            int ar = t >> 2, ac = (t & 3) * 4;
            cp16(sbase + (ar * APu + ac) * 4, &A0[(size_t)(m0 + ar) * Kp + kp0 + ac]);
        }
        #pragma unroll
        for (int t = tid; t < 512; t += 128) {
            int br = t >> 5, bc = (t & 31) * 4;
            cp16(sbase + (SA + br * BPu + bc) * 4, &B0[(size_t)(kp0 + br) * N + n0 + bc]);
            cp16(sbase + (BLO + br * BPu + bc) * 4, &B1[(size_t)(kp0 + br) * N + n0 + bc]);
        }
        CP_COMMIT();
    };

    load_tile(0, 0);
    const int niter = K / 32;
    for (int it = 0; it < niter; it++) {
        const int st = it & 1;
        CP_WAIT0();
        __syncthreads();
        if (it + 1 < niter) load_tile((it + 1) * 16, st ^ 1);

        const unsigned int* Ah = smu + st * ST;
        const unsigned int* Bh = smu + st * ST + SA;
        const unsigned int* Bl = smu + st * ST + BLO;
        #pragma unroll
        for (int ks = 0; ks < 2; ks++) {
            uint32_t ra[4][4], rb[4][2], lb[4][2];
            #pragma unroll
            for (int mt = 0; mt < 4; mt++) {
                const unsigned int* ap = Ah + (mt * 16 + r4) * APu + 8 * ks + 2 * c4l;
                uint2 x0 = *(const uint2*)ap;
                uint2 x1 = *(const uint2*)(ap + 8 * APu);
                ra[mt][0] = x0.x; ra[mt][1] = x1.x; ra[mt][2] = x0.y; ra[mt][3] = x1.y;
            }
            #pragma unroll
            for (int nt = 0; nt < 4; nt++) {
                int cn = wn * 32 + nt * 8 + r4;
                rb[nt][0] = Bh[(8 * ks + c4l) * BPu + cn];
                rb[nt][1] = Bh[(8 * ks + c4l + 4) * BPu + cn];
                lb[nt][0] = Bl[(8 * ks + c4l) * BPu + cn];
                lb[nt][1] = Bl[(8 * ks + c4l + 4) * BPu + cn];
            }
            #pragma unroll
            for (int mt = 0; mt < 4; mt++)
                #pragma unroll
                for (int nt = 0; nt < 4; nt++) {
                    mma16(acc[mt][nt], ra[mt][0], ra[mt][1], ra[mt][2], ra[mt][3],
                          rb[nt][0], rb[nt][1]);
                    mma16(acc[mt][nt], ra[mt][0], ra[mt][1], ra[mt][2], ra[mt][3],
                          lb[nt][0], lb[nt][1]);
                }
        }
    }
    #pragma unroll
    for (int mt = 0; mt < 4; mt++)
        #pragma unroll
        for (int nt = 0; nt < 4; nt++) {
            int row = m0 + mt * 16 + r4;
            int col = n0 + wn * 32 + nt * 8 + 2 * c4l;
            *(float2*)&C[(size_t)row * N + col] =
                make_float2(acc[mt][nt][0], acc[mt][nt][1]);
            *(float2*)&C[(size_t)(row + 8) * N + col] =
                make_float2(acc[mt][nt][2], acc[mt][nt][3]);
        }
}

// ---------------------------------------------------------------------------
// Flash attention fp16, fp16 bias (halved L2 traffic), lp via ones-MMA.
// ---------------------------------------------------------------------------
#define FQ 128
#define FKV 64
#define NIT (P / FKV)
#define OFF_K0 0
#define OFF_K1 2560
#define OFF_V0 5120
#define OFF_V1 7680
#define OFF_P  10240
#define FLASH_SMEM (15360 * 4)
#define ONES2 0x3C003C00u

__global__ __launch_bounds__(256, 2) void flash7(
    const unsigned int* __restrict__ q32, const unsigned int* __restrict__ k32,
    const unsigned int* __restrict__ v32, const unsigned int* __restrict__ bias16,
    unsigned int* __restrict__ ahi) {
    extern __shared__ unsigned int smu[];
    const uint32_t smb = smem_u32(smu);
    const int tid = threadIdx.x, lane = tid & 31, warp = tid >> 5;
    const int r4 = lane >> 2, c4l = lane & 3;
    const int q0 = blockIdx.x * FQ, h = blockIdx.y;
    const int qrow = warp * 16;
    const int grow0 = q0 + qrow + r4, grow1 = grow0 + 8;
    const unsigned int* bp0 = bias16 + ((size_t)grow0 << 10) + c4l;
    const unsigned int* bp1 = bias16 + ((size_t)grow1 << 10) + c4l;

    #pragma unroll
    for (int i = 0; i < 2; i++) {
        int idx = tid + i * 256;
        int r = idx >> 3, seg = (idx & 7) * 4;
        cp16(smb + (OFF_K0 + r * 40 + seg) * 4, &k32[(size_t)r * 512 + h * 32 + seg]);
        cp16(smb + (OFF_V0 + r * 40 + seg) * 4, &v32[(size_t)(h * 64 + r) * 1024 + seg]);
    }
    #pragma unroll
    for (int i = 0; i < 4; i++) {
        int idx = tid + i * 256;
        int row = idx >> 3, seg = (idx & 7) * 4;
        cp16(smb + (OFF_P + row * 40 + seg) * 4, &q32[(size_t)(q0 + row) * 512 + h * 32 + seg]);
    }
    CP_COMMIT();
    CP_WAIT0();
    __syncthreads();

    uint32_t qf[4][4];
    #pragma unroll
    for (int ks = 0; ks < 4; ks++) {
        const unsigned int* qp = smu + OFF_P + (qrow + r4) * 40 + 8 * ks + 2 * c4l;
        uint2 x0 = *(const uint2*)qp;
        uint2 x1 = *(const uint2*)(qp + 8 * 40);
        qf[ks][0] = x0.x; qf[ks][1] = x1.x; qf[ks][2] = x0.y; qf[ks][3] = x1.y;
    }

    float oacc[8][4];
    #pragma unroll
    for (int i = 0; i < 8; i++)
        #pragma unroll
        for (int j = 0; j < 4; j++) oacc[i][j] = 0.f;
    float lacc[4] = {0.f, 0.f, 0.f, 0.f};

    for (int it = 0; it < NIT; it++) {
        const int buf = it & 1;
        const unsigned int* Ks = smu + (buf ? OFF_K1 : OFF_K0);
        const unsigned int* Vs = smu + (buf ? OFF_V1 : OFF_V0);
        CP_WAIT0();
        __syncthreads();

        const int kv0 = it * FKV;
        const int kvp = kv0 >> 1;
        uint32_t bz0[8], bz1[8];
        #pragma unroll
        for (int nt = 0; nt < 8; nt++) {
            bz0[nt] = bp0[kvp + nt * 4];
            bz1[nt] = bp1[kvp + nt * 4];
        }
        if (it + 1 < NIT) {
            const uint32_t ko = buf ? OFF_K0 : OFF_K1;
            const uint32_t vo = buf ? OFF_V0 : OFF_V1;
            #pragma unroll
            for (int i = 0; i < 2; i++) {
                int idx = tid + i * 256;
                int r = idx >> 3, seg = (idx & 7) * 4;
                cp16(smb + (ko + r * 40 + seg) * 4,
                     &k32[(size_t)(kv0 + FKV + r) * 512 + h * 32 + seg]);
                cp16(smb + (vo + r * 40 + seg) * 4,
                     &v32[(size_t)(h * 64 + r) * 1024 + (it + 1) * 32 + seg]);
            }
            CP_COMMIT();
        }

        // S = Q K^T + exp2 (fixed origin), paired nt
        #pragma unroll
        for (int g = 0; g < 4; g++) {
            const int ntA = 2 * g, ntB = 2 * g + 1;
            float sA[4] = {0.f, 0.f, 0.f, 0.f}, sB[4] = {0.f, 0.f, 0.f, 0.f};
            #pragma unroll
            for (int ks = 0; ks < 4; ks++) {
                uint2 ka = *(const uint2*)&Ks[(ntA * 8 + r4) * 40 + 8 * ks + 2 * c4l];
                uint2 kb = *(const uint2*)&Ks[(ntB * 8 + r4) * 40 + 8 * ks + 2 * c4l];
                mma16(sA, qf[ks][0], qf[ks][1], qf[ks][2], qf[ks][3], ka.x, ka.y);
                mma16(sB, qf[ks][0], qf[ks][1], qf[ks][2], qf[ks][3], kb.x, kb.y);
            }
            float2 bA0 = h2up(bz0[ntA]), bA1 = h2up(bz1[ntA]);
            float2 bB0 = h2up(bz0[ntB]), bB1 = h2up(bz1[ntB]);
            float pA0 = exp2f(sA[0] + bA0.x), pA1 = exp2f(sA[1] + bA0.y);
            float pA2 = exp2f(sA[2] + bA1.x), pA3 = exp2f(sA[3] + bA1.y);
            float pB0 = exp2f(sB[0] + bB0.x), pB1 = exp2f(sB[1] + bB0.y);
            float pB2 = exp2f(sB[2] + bB1.x), pB3 = exp2f(sB[3] + bB1.y);
            uint2 w0 = make_uint2(h2pk(pA0, pA1), h2pk(pB0, pB1));
            uint2 w1v = make_uint2(h2pk(pA2, pA3), h2pk(pB2, pB3));
            *(uint2*)&smu[OFF_P + (qrow + r4) * 40 + 8 * g + 2 * c4l]     = w0;
            *(uint2*)&smu[OFF_P + (qrow + 8 + r4) * 40 + 8 * g + 2 * c4l] = w1v;
        }
        __syncwarp();

        // O += P V  and  lp += P @ ones
        #pragma unroll
        for (int ks = 0; ks < 4; ks++) {
            uint2 x0 = *(const uint2*)&smu[OFF_P + (qrow + r4) * 40 + 8 * ks + 2 * c4l];
            uint2 x1 = *(const uint2*)&smu[OFF_P + (qrow + 8 + r4) * 40 + 8 * ks + 2 * c4l];
            #pragma unroll
            for (int nt = 0; nt < 8; nt++) {
                uint2 vb = *(const uint2*)&Vs[(nt * 8 + r4) * 40 + 8 * ks + 2 * c4l];
                mma16(oacc[nt], x0.x, x1.x, x0.y, x1.y, vb.x, vb.y);
            }
            mma16(lacc, x0.x, x1.x, x0.y, x1.y, ONES2, ONES2);
        }
    }

    const float inv0 = 1.f / lacc[0], inv1 = 1.f / lacc[2];
    #pragma unroll
    for (int nt = 0; nt < 8; nt++) {
        const int slot = h * 32 + 8 * (nt >> 1) + 2 * c4l + (nt & 1);
        ahi[(size_t)(q0 + qrow + r4) * 512 + slot] =
            h2pk(oacc[nt][0] * inv0, oacc[nt][1] * inv0);
        ahi[(size_t)(q0 + qrow + 8 + r4) * 512 + slot] =
            h2pk(oacc[nt][2] * inv1, oacc[nt][3] * inv1);
    }
}

// ---------------------------------------------------------------------------
extern "C" void kernel_launch(void* const* d_in, const int* in_sizes, int n_in,
                              void* d_out, int out_size) {
    const float* x      = (const float*)d_in[0];
    const float* rel    = (const float*)d_in[1];
    const float* w_qkv  = (const float*)d_in[2];
    const float* w_proj = (const float*)d_in[3];
    const float* w1     = (const float*)d_in[4];
    const float* b1     = (const float*)d_in[5];
    const float* w2     = (const float*)d_in[6];
    const float* b2     = (const float*)d_in[7];
    const float* w3     = (const float*)d_in[8];
    const float* b3     = (const float*)d_in[9];
    float* out = (float*)d_out;

    unsigned int *q32, *k32, *v32, *xp, *wqp, *wph, *wpl, *ahi, *bias16;
    cudaGetSymbolAddress((void**)&q32, g_q32);
    cudaGetSymbolAddress((void**)&k32, g_k32);
    cudaGetSymbolAddress((void**)&v32, g_v32);
    cudaGetSymbolAddress((void**)&xp,  g_xp);
    cudaGetSymbolAddress((void**)&wqp, g_wqp);
    cudaGetSymbolAddress((void**)&wph, g_wph);
    cudaGetSymbolAddress((void**)&wpl, g_wpl);
    cudaGetSymbolAddress((void**)&ahi, g_ahi);
    cudaGetSymbolAddress((void**)&bias16, g_bias16);

    constexpr int SM_PROJ = 2 * (64 * APu + 2 * 16 * BPu) * 4;
    cudaFuncSetAttribute(combo_qkv_rpb,
                         cudaFuncAttributeMaxDynamicSharedMemorySize, SM_QKV);
    cudaFuncSetAttribute(gemm_proj,
                         cudaFuncAttributeMaxDynamicSharedMemorySize, SM_PROJ);
    cudaFuncSetAttribute(flash7, cudaFuncAttributeMaxDynamicSharedMemorySize, FLASH_SMEM);

    // 1) fused packs
    pack_all<<<(NPA + NPB + NPC) / 256, 256>>>(x, w_qkv, w_proj, xp, wqp, wph, wpl);
    // 2) qkv GEMM || RPB MLP, interleaved roles
    combo_qkv_rpb<<<19 * 128, 256, SM_QKV>>>(
        xp, wqp, q32, k32, (__half*)v32, rel, w1, b1, w2, b2, w3, b3, bias16);
    // 3) flash attention
    flash7<<<dim3(P / FQ, H), 256, FLASH_SMEM>>>(q32, k32, v32, bias16, ahi);
    // 4) proj
    gemm_proj<<<dim3(D / 128, P / 64), 128, SM_PROJ>>>(
        ahi, wph, wpl, out, P, D, D);
}

// round 12
// speedup vs baseline: 1.0516x; 1.0516x over previous
#include <cuda_runtime.h>
#include <cuda_fp16.h>
#include <math.h>
#include <stdint.h>

#define P 2048
#define D 1024
#define H 16
#define DH 64
#define HID 32
#define P3D 3072
#define LOG2E 1.44269504088896f

__device__ unsigned int g_q32[P * 512];        // [P][D/2] tau-packed, q*log2e/8
__device__ unsigned int g_k32[P * 512];        // [P][D/2] tau-packed
__device__ unsigned int g_v32[H * 64 * 1024];  // [H][64 d][1024 kvpair tau-slots]
__device__ unsigned int g_xp[P * 512];         // x tau-packed
__device__ unsigned int g_wqp[512 * P3D];      // w_qkv kpair-packed [D/2][3D]
__device__ unsigned int g_wph[512 * D];        // w_proj hi kpair-packed
__device__ unsigned int g_wpl[512 * D];
__device__ unsigned int g_ahi[P * 512];        // att tau-packed
__device__ unsigned int g_bias16[P * 1024];    // bias*log2e, half2-packed [P][P/2]

__device__ __forceinline__ int tau(int w) { return ((w & 3) << 1) | (w >> 2); }
__device__ __forceinline__ uint32_t h2pk(float a, float b) {
    __half2 h = __floats2half2_rn(a, b);
    return *reinterpret_cast<uint32_t*>(&h);
}
__device__ __forceinline__ uint32_t smem_u32(const void* p) {
    uint32_t a;
    asm("{ .reg .u64 t; cvta.to.shared.u64 t, %1; cvt.u32.u64 %0, t; }" : "=r"(a) : "l"(p));
    return a;
}
__device__ __forceinline__ uint32_t hadd2u(uint32_t a, uint32_t b) {
    uint32_t r; asm("add.f16x2 %0, %1, %2;" : "=r"(r) : "r"(a), "r"(b)); return r;
}
__device__ __forceinline__ uint32_t ex2h2(uint32_t a) {
    uint32_t r; asm("ex2.approx.f16x2 %0, %1;" : "=r"(r) : "r"(a)); return r;
}
__device__ __forceinline__ void mma16(float c[4], uint32_t a0, uint32_t a1,
                                      uint32_t a2, uint32_t a3,
                                      uint32_t b0, uint32_t b1) {
    asm volatile(
        "mma.sync.aligned.m16n8k16.row.col.f32.f16.f16.f32 "
        "{%0,%1,%2,%3},{%4,%5,%6,%7},{%8,%9},{%0,%1,%2,%3};\n"
        : "+f"(c[0]), "+f"(c[1]), "+f"(c[2]), "+f"(c[3])
        : "r"(a0), "r"(a1), "r"(a2), "r"(a3), "r"(b0), "r"(b1));
}
__device__ __forceinline__ void cp16(uint32_t dst, const void* src) {
    asm volatile("cp.async.ca.shared.global [%0], [%1], 16;" :: "r"(dst), "l"(src));
}
#define CP_COMMIT() asm volatile("cp.async.commit_group;" ::: "memory")
#define CP_WAIT0()  asm volatile("cp.async.wait_group 0;" ::: "memory")

// ---------------------------------------------------------------------------
// Single fused pack pre-pass
// ---------------------------------------------------------------------------
#define NPA (P * 512)
#define NPB (512 * P3D)
#define NPC (512 * D)

__global__ void pack_all(const float* __restrict__ x, const float* __restrict__ wq,
                         const float* __restrict__ wp,
                         unsigned int* __restrict__ xp, unsigned int* __restrict__ wqp,
                         unsigned int* __restrict__ wph, unsigned int* __restrict__ wpl) {
    int i = blockIdx.x * blockDim.x + threadIdx.x;
    if (i < NPA) {
        int row = i >> 9, p = i & 511;
        int slot = (p & ~7) | tau(p & 7);
        xp[((size_t)row << 9) + slot] =
            h2pk(x[(size_t)row * 1024 + 2 * p], x[(size_t)row * 1024 + 2 * p + 1]);
    } else if (i < NPA + NPB) {
        int j = i - NPA;
        int kp = j / P3D, n = j % P3D;
        wqp[j] = h2pk(wq[(size_t)(2 * kp) * P3D + n], wq[(size_t)(2 * kp + 1) * P3D + n]);
    } else {
        int j = i - NPA - NPB;
        int kp = j >> 10, n = j & 1023;
        float v0 = wp[(size_t)(2 * kp) * D + n], v1 = wp[(size_t)(2 * kp + 1) * D + n];
        __half h0 = __float2half_rn(v0), h1 = __float2half_rn(v1);
        wph[j] = h2pk(__half2float(h0), __half2float(h1));
        wpl[j] = h2pk(v0 - __half2float(h0), v1 - __half2float(h1));
    }
}

// ---------------------------------------------------------------------------
// Combo kernel: SEQUENTIAL roles (blocks [0,384) qkv, rest rpb) — round-10
// ordering; interleave measured as a regression under the 2-CTA/SM cap.
// ---------------------------------------------------------------------------
#define APu 24
#define BPu 136
#define QKV_SA (128 * APu)
#define QKV_SB (16 * BPu)
#define QKV_ST (QKV_SA + QKV_SB)
#define SM_QKV (2 * QKV_ST * 4)      // 41,984 B
#define NQKV_BLK 384
#define NRPB_BLK 2048
#define HPt 24

__global__ __launch_bounds__(256, 2) void combo_qkv_rpb(
    const unsigned int* __restrict__ A0, const unsigned int* __restrict__ B0,
    unsigned int* __restrict__ Cq, unsigned int* __restrict__ Ck,
    __half* __restrict__ Cv,
    const float* __restrict__ rel,
    const float* __restrict__ w1, const float* __restrict__ b1,
    const float* __restrict__ w2, const float* __restrict__ b2,
    const float* __restrict__ w3, const float* __restrict__ b3,
    unsigned int* __restrict__ bias16) {
    extern __shared__ unsigned int smu[];
    const int tid = threadIdx.x, lane = tid & 31, warp = tid >> 5;
    const int r4 = lane >> 2, c4l = lane & 3;

    if (blockIdx.x < NQKV_BLK) {
        // ------------------------- qkv GEMM body --------------------------
        const uint32_t smb = smem_u32(smu);
        const int wm = warp >> 2, wn = warp & 3;
        const int bx = blockIdx.x;
        const int n0 = (bx % 24) * 128, m0 = (bx / 24) * 128;
        const int Kp = 512;
        const int N = P3D;

        float acc[4][4][4];
        #pragma unroll
        for (int i = 0; i < 4; i++)
            #pragma unroll
            for (int j = 0; j < 4; j++)
                #pragma unroll
                for (int q = 0; q < 4; q++) acc[i][j][q] = 0.f;

        auto load_tile = [&](int kp0, int st) {
            const uint32_t sbase = smb + st * QKV_ST * 4;
            #pragma unroll
            for (int t = tid; t < 512; t += 256) {
                int ar = t >> 2, ac = (t & 3) * 4;
                cp16(sbase + (ar * APu + ac) * 4, &A0[(size_t)(m0 + ar) * Kp + kp0 + ac]);
            }
            #pragma unroll
            for (int t = tid; t < 512; t += 256) {
                int br = t >> 5, bc = (t & 31) * 4;
                cp16(sbase + (QKV_SA + br * BPu + bc) * 4,
                     &B0[(size_t)(kp0 + br) * N + n0 + bc]);
            }
            CP_COMMIT();
        };

        load_tile(0, 0);
        for (int it = 0; it < 32; it++) {
            const int st = it & 1;
            CP_WAIT0();
            __syncthreads();
            if (it + 1 < 32) load_tile((it + 1) * 16, st ^ 1);

            const unsigned int* Ah = smu + st * QKV_ST;
            const unsigned int* Bh = smu + st * QKV_ST + QKV_SA;
            #pragma unroll
            for (int ks = 0; ks < 2; ks++) {
                uint32_t ra[4][4], rb[4][2];
                #pragma unroll
                for (int mt = 0; mt < 4; mt++) {
                    const unsigned int* ap =
                        Ah + (wm * 64 + mt * 16 + r4) * APu + 8 * ks + 2 * c4l;
                    uint2 x0 = *(const uint2*)ap;
                    uint2 x1 = *(const uint2*)(ap + 8 * APu);
                    ra[mt][0] = x0.x; ra[mt][1] = x1.x; ra[mt][2] = x0.y; ra[mt][3] = x1.y;
                }
                #pragma unroll
                for (int nt = 0; nt < 4; nt++) {
                    int cn = wn * 32 + nt * 8 + r4;
                    rb[nt][0] = Bh[(8 * ks + c4l) * BPu + cn];
                    rb[nt][1] = Bh[(8 * ks + c4l + 4) * BPu + cn];
                }
                #pragma unroll
                for (int mt = 0; mt < 4; mt++)
                    #pragma unroll
                    for (int nt = 0; nt < 4; nt++)
                        mma16(acc[mt][nt], ra[mt][0], ra[mt][1], ra[mt][2], ra[mt][3],
                              rb[nt][0], rb[nt][1]);
            }
        }

        #pragma unroll
        for (int mt = 0; mt < 4; mt++)
            #pragma unroll
            for (int nt = 0; nt < 4; nt++) {
                int row = m0 + wm * 64 + mt * 16 + r4;
                int col = n0 + wn * 32 + nt * 8 + 2 * c4l;
                float v0 = acc[mt][nt][0], v1 = acc[mt][nt][1];
                float v2 = acc[mt][nt][2], v3 = acc[mt][nt][3];
                if (col < 2 * D) {           // Q,K -> tau-packed half2
                    const float sc = (col < D) ? (0.125f * LOG2E) : 1.0f;
                    const int dd = col & 1023;
                    const int hh = dd >> 6, dh = dd & 63;
                    const int pr = dh >> 1;
                    const int slot = hh * 32 + ((pr & ~7) | tau(pr & 7));
                    unsigned int* dst = (col < D) ? Cq : Ck;
                    dst[(size_t)row * 512 + slot]       = h2pk(v0 * sc, v1 * sc);
                    dst[(size_t)(row + 8) * 512 + slot] = h2pk(v2 * sc, v3 * sc);
                } else {                     // V -> transposed [h][d][kvslot]
                    const int dd = col - 2 * D;
                    const int hh = dd >> 6, dh = dd & 63;
                    const int kp = row >> 1, par = row & 1;
                    const int slot  = (kp & ~7) | tau(kp & 7);
                    const int slot8 = (kp & ~7) | tau((kp & 7) + 4);
                    __half* vb  = Cv + (((size_t)(hh * 64 + dh) << 10) + slot) * 2 + par;
                    __half* vb8 = Cv + (((size_t)(hh * 64 + dh) << 10) + slot8) * 2 + par;
                    vb[0]     = __float2half_rn(v0);
                    vb[2048]  = __float2half_rn(v1);
                    vb8[0]    = __float2half_rn(v2);
                    vb8[2048] = __float2half_rn(v3);
                }
            }
    } else {
        // --------------------------- RPB body ------------------------------
        __shared__ unsigned int h1s[8][16][HPt];

        uint32_t w1b0[4];
        float b1c[4][2], b2c[4][2], w3c[4][2];
        uint32_t w2f[2][4][2];
        #pragma unroll
        for (int nt = 0; nt < 4; nt++) {
            const int n = nt * 8 + r4;
            w1b0[nt] = (c4l == 0) ? h2pk(w1[n], w1[HID + n]) : 0u;
            const int cc = nt * 8 + 2 * c4l;
            b1c[nt][0] = b1[cc]; b1c[nt][1] = b1[cc + 1];
            b2c[nt][0] = b2[cc]; b2c[nt][1] = b2[cc + 1];
            w3c[nt][0] = w3[cc]; w3c[nt][1] = w3[cc + 1];
            #pragma unroll
            for (int ks = 0; ks < 2; ks++) {
                w2f[ks][nt][0] = h2pk(w2[(16 * ks + 2 * c4l) * HID + n],
                                      w2[(16 * ks + 2 * c4l + 1) * HID + n]);
                w2f[ks][nt][1] = h2pk(w2[(16 * ks + 2 * c4l + 8) * HID + n],
                                      w2[(16 * ks + 2 * c4l + 9) * HID + n]);
            }
        }
        const float b3v = b3[0];

        unsigned int (*h1)[HPt] = h1s[warp];
        const int gw = (blockIdx.x - NQKV_BLK) * 8 + warp;
        const int nW = NRPB_BLK * 8;
        for (int task = gw; task < (P * P) / 16; task += nW) {
            const int base = task * 16;
            const float2 ra = *(const float2*)&rel[(size_t)(base + r4) * 2];
            const float2 rb = *(const float2*)&rel[(size_t)(base + 8 + r4) * 2];
            const uint32_t a0 = (c4l == 0) ? h2pk(ra.x, ra.y) : 0u;
            const uint32_t a1 = (c4l == 0) ? h2pk(rb.x, rb.y) : 0u;

            float c1[4][4];
            #pragma unroll
            for (int nt = 0; nt < 4; nt++) {
                c1[nt][0] = b1c[nt][0]; c1[nt][1] = b1c[nt][1];
                c1[nt][2] = b1c[nt][0]; c1[nt][3] = b1c[nt][1];
                mma16(c1[nt], a0, a1, 0u, 0u, w1b0[nt], 0u);
            }
            #pragma unroll
            for (int g = 0; g < 2; g++) {
                uint2 w0 = make_uint2(
                    h2pk(fmaxf(c1[2*g][0], 0.f),   fmaxf(c1[2*g][1], 0.f)),
                    h2pk(fmaxf(c1[2*g+1][0], 0.f), fmaxf(c1[2*g+1][1], 0.f)));
                uint2 w1v = make_uint2(
                    h2pk(fmaxf(c1[2*g][2], 0.f),   fmaxf(c1[2*g][3], 0.f)),
                    h2pk(fmaxf(c1[2*g+1][2], 0.f), fmaxf(c1[2*g+1][3], 0.f)));
                *(uint2*)&h1[r4][8 * g + 2 * c4l]     = w0;
                *(uint2*)&h1[r4 + 8][8 * g + 2 * c4l] = w1v;
            }
            __syncwarp();
            float c2[4][4];
            #pragma unroll
            for (int nt = 0; nt < 4; nt++) {
                c2[nt][0] = b2c[nt][0]; c2[nt][1] = b2c[nt][1];
                c2[nt][2] = b2c[nt][0]; c2[nt][3] = b2c[nt][1];
            }
            #pragma unroll
            for (int ks = 0; ks < 2; ks++) {
                uint2 x0 = *(const uint2*)&h1[r4][8 * ks + 2 * c4l];
                uint2 x1 = *(const uint2*)&h1[r4 + 8][8 * ks + 2 * c4l];
                #pragma unroll
                for (int nt = 0; nt < 4; nt++)
                    mma16(c2[nt], x0.x, x1.x, x0.y, x1.y, w2f[ks][nt][0], w2f[ks][nt][1]);
            }
            float o0 = 0.f, o1 = 0.f;
            #pragma unroll
            for (int nt = 0; nt < 4; nt++) {
                o0 += fmaxf(c2[nt][0], 0.f) * w3c[nt][0] + fmaxf(c2[nt][1], 0.f) * w3c[nt][1];
                o1 += fmaxf(c2[nt][2], 0.f) * w3c[nt][0] + fmaxf(c2[nt][3], 0.f) * w3c[nt][1];
            }
            o0 += __shfl_xor_sync(0xffffffffu, o0, 1);
            o0 += __shfl_xor_sync(0xffffffffu, o0, 2);
            o1 += __shfl_xor_sync(0xffffffffu, o1, 1);
            o1 += __shfl_xor_sync(0xffffffffu, o1, 2);
            float o0n = __shfl_down_sync(0xffffffffu, o0, 4);
            float o1n = __shfl_down_sync(0xffffffffu, o1, 4);
            if (c4l == 0 && !(r4 & 1)) {
                const int pb = base >> 1;
                bias16[pb + (r4 >> 1)]     = h2pk((o0 + b3v) * LOG2E, (o0n + b3v) * LOG2E);
                bias16[pb + 4 + (r4 >> 1)] = h2pk((o1 + b3v) * LOG2E, (o1n + b3v) * LOG2E);
            }
            __syncwarp();
        }
    }
}

// ---------------------------------------------------------------------------
// fp16 proj GEMM (B hi/lo split, 2 MMAs), occupancy 3.
// ---------------------------------------------------------------------------
__global__ __launch_bounds__(128, 3) void gemm_proj(
    const unsigned int* __restrict__ A0,
    const unsigned int* __restrict__ B0, const unsigned int* __restrict__ B1,
    float* __restrict__ C, int M, int N, int K) {
    constexpr int SA = 64 * APu;
    constexpr int SB = 16 * BPu;
    constexpr int BLO = SA + SB;
    constexpr int ST  = SA + 2 * SB;
    extern __shared__ unsigned int smu[];
    const uint32_t smb = smem_u32(smu);

    const int tid = threadIdx.x, lane = tid & 31, warp = tid >> 5;
    const int wn = warp & 3;
    const int m0 = blockIdx.y * 64, n0 = blockIdx.x * 128;
    const int r4 = lane >> 2, c4l = lane & 3;
    const int Kp = K / 2;

    float acc[4][4][4];
    #pragma unroll
    for (int i = 0; i < 4; i++)
        #pragma unroll
        for (int j = 0; j < 4; j++)
            #pragma unroll
            for (int q = 0; q < 4; q++) acc[i][j][q] = 0.f;

    auto load_tile = [&](int kp0, int st) {
        const uint32_t sbase = smb + st * ST * 4;
        #pragma unroll
        for (int t = tid; t < 256; t += 128) {
            int ar = t >> 2, ac = (t & 3) * 4;
            cp16(sbase + (ar * APu + ac) * 4, &A0[(size_t)(m0 + ar) * Kp + kp0 + ac]);
        }
        #pragma unroll
        for (int t = tid; t < 512; t += 128) {
            int br = t >> 5, bc = (t & 31) * 4;
            cp16(sbase + (SA + br * BPu + bc) * 4, &B0[(size_t)(kp0 + br) * N + n0 + bc]);
            cp16(sbase + (BLO + br * BPu + bc) * 4, &B1[(size_t)(kp0 + br) * N + n0 + bc]);
        }
        CP_COMMIT();
    };

    load_tile(0, 0);
    const int niter = K / 32;
    for (int it = 0; it < niter; it++) {
        const int st = it & 1;
        CP_WAIT0();
        __syncthreads();
        if (it + 1 < niter) load_tile((it + 1) * 16, st ^ 1);

        const unsigned int* Ah = smu + st * ST;
        const unsigned int* Bh = smu + st * ST + SA;
        const unsigned int* Bl = smu + st * ST + BLO;
        #pragma unroll
        for (int ks = 0; ks < 2; ks++) {
            uint32_t ra[4][4], rb[4][2], lb[4][2];
            #pragma unroll
            for (int mt = 0; mt < 4; mt++) {
                const unsigned int* ap = Ah + (mt * 16 + r4) * APu + 8 * ks + 2 * c4l;
                uint2 x0 = *(const uint2*)ap;
                uint2 x1 = *(const uint2*)(ap + 8 * APu);
                ra[mt][0] = x0.x; ra[mt][1] = x1.x; ra[mt][2] = x0.y; ra[mt][3] = x1.y;
            }
            #pragma unroll
            for (int nt = 0; nt < 4; nt++) {
                int cn = wn * 32 + nt * 8 + r4;
                rb[nt][0] = Bh[(8 * ks + c4l) * BPu + cn];
                rb[nt][1] = Bh[(8 * ks + c4l + 4) * BPu + cn];
                lb[nt][0] = Bl[(8 * ks + c4l) * BPu + cn];
                lb[nt][1] = Bl[(8 * ks + c4l + 4) * BPu + cn];
            }
            #pragma unroll
            for (int mt = 0; mt < 4; mt++)
                #pragma unroll
                for (int nt = 0; nt < 4; nt++) {
                    mma16(acc[mt][nt], ra[mt][0], ra[mt][1], ra[mt][2], ra[mt][3],
                          rb[nt][0], rb[nt][1]);
                    mma16(acc[mt][nt], ra[mt][0], ra[mt][1], ra[mt][2], ra[mt][3],
                          lb[nt][0], lb[nt][1]);
                }
        }
    }
    #pragma unroll
    for (int mt = 0; mt < 4; mt++)
        #pragma unroll
        for (int nt = 0; nt < 4; nt++) {
            int row = m0 + mt * 16 + r4;
            int col = n0 + wn * 32 + nt * 8 + 2 * c4l;
            *(float2*)&C[(size_t)row * N + col] =
                make_float2(acc[mt][nt][0], acc[mt][nt][1]);
            *(float2*)&C[(size_t)(row + 8) * N + col] =
                make_float2(acc[mt][nt][2], acc[mt][nt][3]);
        }
}

// ---------------------------------------------------------------------------
// Flash attention fp16: fp16x2 softmax (pack -> HADD2 bias16 -> ex2.approx.f16x2),
// lp via ones-MMA, fixed softmax origin.
// ---------------------------------------------------------------------------
#define FQ 128
#define FKV 64
#define NIT (P / FKV)
#define OFF_K0 0
#define OFF_K1 2560
#define OFF_V0 5120
#define OFF_V1 7680
#define OFF_P  10240
#define FLASH_SMEM (15360 * 4)
#define ONES2 0x3C003C00u

__global__ __launch_bounds__(256, 2) void flash8(
    const unsigned int* __restrict__ q32, const unsigned int* __restrict__ k32,
    const unsigned int* __restrict__ v32, const unsigned int* __restrict__ bias16,
    unsigned int* __restrict__ ahi) {
    extern __shared__ unsigned int smu[];
    const uint32_t smb = smem_u32(smu);
    const int tid = threadIdx.x, lane = tid & 31, warp = tid >> 5;
    const int r4 = lane >> 2, c4l = lane & 3;
    const int q0 = blockIdx.x * FQ, h = blockIdx.y;
    const int qrow = warp * 16;
    const int grow0 = q0 + qrow + r4, grow1 = grow0 + 8;
    const unsigned int* bp0 = bias16 + ((size_t)grow0 << 10) + c4l;
    const unsigned int* bp1 = bias16 + ((size_t)grow1 << 10) + c4l;

    #pragma unroll
    for (int i = 0; i < 2; i++) {
        int idx = tid + i * 256;
        int r = idx >> 3, seg = (idx & 7) * 4;
        cp16(smb + (OFF_K0 + r * 40 + seg) * 4, &k32[(size_t)r * 512 + h * 32 + seg]);
        cp16(smb + (OFF_V0 + r * 40 + seg) * 4, &v32[(size_t)(h * 64 + r) * 1024 + seg]);
    }
    #pragma unroll
    for (int i = 0; i < 4; i++) {
        int idx = tid + i * 256;
        int row = idx >> 3, seg = (idx & 7) * 4;
        cp16(smb + (OFF_P + row * 40 + seg) * 4, &q32[(size_t)(q0 + row) * 512 + h * 32 + seg]);
    }
    CP_COMMIT();
    CP_WAIT0();
    __syncthreads();

    uint32_t qf[4][4];
    #pragma unroll
    for (int ks = 0; ks < 4; ks++) {
        const unsigned int* qp = smu + OFF_P + (qrow + r4) * 40 + 8 * ks + 2 * c4l;
        uint2 x0 = *(const uint2*)qp;
        uint2 x1 = *(const uint2*)(qp + 8 * 40);
        qf[ks][0] = x0.x; qf[ks][1] = x1.x; qf[ks][2] = x0.y; qf[ks][3] = x1.y;
    }

    float oacc[8][4];
    #pragma unroll
    for (int i = 0; i < 8; i++)
        #pragma unroll
        for (int j = 0; j < 4; j++) oacc[i][j] = 0.f;
    float lacc[4] = {0.f, 0.f, 0.f, 0.f};

    for (int it = 0; it < NIT; it++) {
        const int buf = it & 1;
        const unsigned int* Ks = smu + (buf ? OFF_K1 : OFF_K0);
        const unsigned int* Vs = smu + (buf ? OFF_V1 : OFF_V0);
        CP_WAIT0();
        __syncthreads();

        const int kv0 = it * FKV;
        const int kvp = kv0 >> 1;
        uint32_t bz0[8], bz1[8];
        #pragma unroll
        for (int nt = 0; nt < 8; nt++) {
            bz0[nt] = bp0[kvp + nt * 4];
            bz1[nt] = bp1[kvp + nt * 4];
        }
        if (it + 1 < NIT) {
            const uint32_t ko = buf ? OFF_K0 : OFF_K1;
            const uint32_t vo = buf ? OFF_V0 : OFF_V1;
            #pragma unroll
            for (int i = 0; i < 2; i++) {
                int idx = tid + i * 256;
                int r = idx >> 3, seg = (idx & 7) * 4;
                cp16(smb + (ko + r * 40 + seg) * 4,
                     &k32[(size_t)(kv0 + FKV + r) * 512 + h * 32 + seg]);
                cp16(smb + (vo + r * 40 + seg) * 4,
                     &v32[(size_t)(h * 64 + r) * 1024 + (it + 1) * 32 + seg]);
            }
            CP_COMMIT();
        }

        // S = Q K^T, fp16x2 softmax (HADD2 bias + ex2.approx.f16x2)
        #pragma unroll
        for (int g = 0; g < 4; g++) {
            const int ntA = 2 * g, ntB = 2 * g + 1;
            float sA[4] = {0.f, 0.f, 0.f, 0.f}, sB[4] = {0.f, 0.f, 0.f, 0.f};
            #pragma unroll
            for (int ks = 0; ks < 4; ks++) {
                uint2 ka = *(const uint2*)&Ks[(ntA * 8 + r4) * 40 + 8 * ks + 2 * c4l];
                uint2 kb = *(const uint2*)&Ks[(ntB * 8 + r4) * 40 + 8 * ks + 2 * c4l];
                mma16(sA, qf[ks][0], qf[ks][1], qf[ks][2], qf[ks][3], ka.x, ka.y);
                mma16(sB, qf[ks][0], qf[ks][1], qf[ks][2], qf[ks][3], kb.x, kb.y);
            }
            uint32_t pA01 = ex2h2(hadd2u(h2pk(sA[0], sA[1]), bz0[ntA]));
            uint32_t pA23 = ex2h2(hadd2u(h2pk(sA[2], sA[3]), bz1[ntA]));
            uint32_t pB01 = ex2h2(hadd2u(h2pk(sB[0], sB[1]), bz0[ntB]));
            uint32_t pB23 = ex2h2(hadd2u(h2pk(sB[2], sB[3]), bz1[ntB]));
            *(uint2*)&smu[OFF_P + (qrow + r4) * 40 + 8 * g + 2 * c4l] =
                make_uint2(pA01, pB01);
            *(uint2*)&smu[OFF_P + (qrow + 8 + r4) * 40 + 8 * g + 2 * c4l] =
                make_uint2(pA23, pB23);
        }
        __syncwarp();

        // O += P V  and  lp += P @ ones
        #pragma unroll
        for (int ks = 0; ks < 4; ks++) {
            uint2 x0 = *(const uint2*)&smu[OFF_P + (qrow + r4) * 40 + 8 * ks + 2 * c4l];
            uint2 x1 = *(const uint2*)&smu[OFF_P + (qrow + 8 + r4) * 40 + 8 * ks + 2 * c4l];
            #pragma unroll
            for (int nt = 0; nt < 8; nt++) {
                uint2 vb = *(const uint2*)&Vs[(nt * 8 + r4) * 40 + 8 * ks + 2 * c4l];
                mma16(oacc[nt], x0.x, x1.x, x0.y, x1.y, vb.x, vb.y);
            }
            mma16(lacc, x0.x, x1.x, x0.y, x1.y, ONES2, ONES2);
        }
    }

    const float inv0 = 1.f / lacc[0], inv1 = 1.f / lacc[2];
    #pragma unroll
    for (int nt = 0; nt < 8; nt++) {
        const int slot = h * 32 + 8 * (nt >> 1) + 2 * c4l + (nt & 1);
        ahi[(size_t)(q0 + qrow + r4) * 512 + slot] =
            h2pk(oacc[nt][0] * inv0, oacc[nt][1] * inv0);
        ahi[(size_t)(q0 + qrow + 8 + r4) * 512 + slot] =
            h2pk(oacc[nt][2] * inv1, oacc[nt][3] * inv1);
    }
}

// ---------------------------------------------------------------------------
extern "C" void kernel_launch(void* const* d_in, const int* in_sizes, int n_in,
                              void* d_out, int out_size) {
    const float* x      = (const float*)d_in[0];
    const float* rel    = (const float*)d_in[1];
    const float* w_qkv  = (const float*)d_in[2];
    const float* w_proj = (const float*)d_in[3];
    const float* w1     = (const float*)d_in[4];
    const float* b1     = (const float*)d_in[5];
    const float* w2     = (const float*)d_in[6];
    const float* b2     = (const float*)d_in[7];
    const float* w3     = (const float*)d_in[8];
    const float* b3     = (const float*)d_in[9];
    float* out = (float*)d_out;

    unsigned int *q32, *k32, *v32, *xp, *wqp, *wph, *wpl, *ahi, *bias16;
    cudaGetSymbolAddress((void**)&q32, g_q32);
    cudaGetSymbolAddress((void**)&k32, g_k32);
    cudaGetSymbolAddress((void**)&v32, g_v32);
    cudaGetSymbolAddress((void**)&xp,  g_xp);
    cudaGetSymbolAddress((void**)&wqp, g_wqp);
    cudaGetSymbolAddress((void**)&wph, g_wph);
    cudaGetSymbolAddress((void**)&wpl, g_wpl);
    cudaGetSymbolAddress((void**)&ahi, g_ahi);
    cudaGetSymbolAddress((void**)&bias16, g_bias16);

    constexpr int SM_PROJ = 2 * (64 * APu + 2 * 16 * BPu) * 4;
    cudaFuncSetAttribute(combo_qkv_rpb,
                         cudaFuncAttributeMaxDynamicSharedMemorySize, SM_QKV);
    cudaFuncSetAttribute(gemm_proj,
                         cudaFuncAttributeMaxDynamicSharedMemorySize, SM_PROJ);
    cudaFuncSetAttribute(flash8, cudaFuncAttributeMaxDynamicSharedMemorySize, FLASH_SMEM);

    // 1) fused packs
    pack_all<<<(NPA + NPB + NPC) / 256, 256>>>(x, w_qkv, w_proj, xp, wqp, wph, wpl);
    // 2) qkv GEMM || RPB MLP (sequential roles — round-10 ordering)
    combo_qkv_rpb<<<NQKV_BLK + NRPB_BLK, 256, SM_QKV>>>(
        xp, wqp, q32, k32, (__half*)v32, rel, w1, b1, w2, b2, w3, b3, bias16);
    // 3) flash attention
    flash8<<<dim3(P / FQ, H), 256, FLASH_SMEM>>>(q32, k32, v32, bias16, ahi);
    // 4) proj
    gemm_proj<<<dim3(D / 128, P / 64), 128, SM_PROJ>>>(
        ahi, wph, wpl, out, P, D, D);
}

// round 13
// speedup vs baseline: 1.0668x; 1.0144x over previous
#include <cuda_runtime.h>
#include <cuda_fp16.h>
#include <math.h>
#include <stdint.h>

#define P 2048
#define D 1024
#define H 16
#define DH 64
#define HID 32
#define P3D 3072
#define LOG2E 1.44269504088896f

__device__ unsigned int g_q32[P * 512];        // [P][D/2] tau-packed, q*log2e/8
__device__ unsigned int g_k32[P * 512];        // [P][D/2] tau-packed
__device__ unsigned int g_v32[H * 64 * 1024];  // [H][64 d][1024 kvpair tau-slots]
__device__ unsigned int g_xp[P * 512];         // x tau-packed
__device__ unsigned int g_wqp[512 * P3D];      // w_qkv kpair-packed [D/2][3D]
__device__ unsigned int g_wph[512 * D];        // w_proj hi kpair-packed
__device__ unsigned int g_wpl[512 * D];
__device__ unsigned int g_ahi[P * 512];        // att tau-packed
__device__ unsigned int g_bias16[P * 1024];    // bias*log2e, half2-packed [P][P/2]

__device__ __forceinline__ int tau(int w) { return ((w & 3) << 1) | (w >> 2); }
__device__ __forceinline__ uint32_t h2pk(float a, float b) {
    __half2 h = __floats2half2_rn(a, b);
    return *reinterpret_cast<uint32_t*>(&h);
}
__device__ __forceinline__ uint32_t smem_u32(const void* p) {
    uint32_t a;
    asm("{ .reg .u64 t; cvta.to.shared.u64 t, %1; cvt.u32.u64 %0, t; }" : "=r"(a) : "l"(p));
    return a;
}
__device__ __forceinline__ uint32_t hadd2u(uint32_t a, uint32_t b) {
    uint32_t r; asm("add.f16x2 %0, %1, %2;" : "=r"(r) : "r"(a), "r"(b)); return r;
}
__device__ __forceinline__ uint32_t ex2h2(uint32_t a) {
    uint32_t r; asm("ex2.approx.f16x2 %0, %1;" : "=r"(r) : "r"(a)); return r;
}
__device__ __forceinline__ void mma16(float c[4], uint32_t a0, uint32_t a1,
                                      uint32_t a2, uint32_t a3,
                                      uint32_t b0, uint32_t b1) {
    asm volatile(
        "mma.sync.aligned.m16n8k16.row.col.f32.f16.f16.f32 "
        "{%0,%1,%2,%3},{%4,%5,%6,%7},{%8,%9},{%0,%1,%2,%3};\n"
        : "+f"(c[0]), "+f"(c[1]), "+f"(c[2]), "+f"(c[3])
        : "r"(a0), "r"(a1), "r"(a2), "r"(a3), "r"(b0), "r"(b1));
}
__device__ __forceinline__ void cp16(uint32_t dst, const void* src) {
    asm volatile("cp.async.ca.shared.global [%0], [%1], 16;" :: "r"(dst), "l"(src));
}
#define CP_COMMIT() asm volatile("cp.async.commit_group;" ::: "memory")
#define CP_WAIT0()  asm volatile("cp.async.wait_group 0;" ::: "memory")

// ---------------------------------------------------------------------------
// Single fused pack pre-pass
// ---------------------------------------------------------------------------
#define NPA (P * 512)
#define NPB (512 * P3D)
#define NPC (512 * D)

__global__ void pack_all(const float* __restrict__ x, const float* __restrict__ wq,
                         const float* __restrict__ wp,
                         unsigned int* __restrict__ xp, unsigned int* __restrict__ wqp,
                         unsigned int* __restrict__ wph, unsigned int* __restrict__ wpl) {
    int i = blockIdx.x * blockDim.x + threadIdx.x;
    if (i < NPA) {
        int row = i >> 9, p = i & 511;
        int slot = (p & ~7) | tau(p & 7);
        xp[((size_t)row << 9) + slot] =
            h2pk(x[(size_t)row * 1024 + 2 * p], x[(size_t)row * 1024 + 2 * p + 1]);
    } else if (i < NPA + NPB) {
        int j = i - NPA;
        int kp = j / P3D, n = j % P3D;
        wqp[j] = h2pk(wq[(size_t)(2 * kp) * P3D + n], wq[(size_t)(2 * kp + 1) * P3D + n]);
    } else {
        int j = i - NPA - NPB;
        int kp = j >> 10, n = j & 1023;
        float v0 = wp[(size_t)(2 * kp) * D + n], v1 = wp[(size_t)(2 * kp + 1) * D + n];
        __half h0 = __float2half_rn(v0), h1 = __float2half_rn(v1);
        wph[j] = h2pk(__half2float(h0), __half2float(h1));
        wpl[j] = h2pk(v0 - __half2float(h0), v1 - __half2float(h1));
    }
}

// ---------------------------------------------------------------------------
// Combo kernel: sequential roles (blocks [0,384) qkv, rest rpb).
// ---------------------------------------------------------------------------
#define APu 24
#define BPu 136
#define QKV_SA (128 * APu)
#define QKV_SB (16 * BPu)
#define QKV_ST (QKV_SA + QKV_SB)
#define SM_QKV (2 * QKV_ST * 4)      // 41,984 B
#define NQKV_BLK 384
#define NRPB_BLK 2048
#define HPt 24

__global__ __launch_bounds__(256, 2) void combo_qkv_rpb(
    const unsigned int* __restrict__ A0, const unsigned int* __restrict__ B0,
    unsigned int* __restrict__ Cq, unsigned int* __restrict__ Ck,
    __half* __restrict__ Cv,
    const float* __restrict__ rel,
    const float* __restrict__ w1, const float* __restrict__ b1,
    const float* __restrict__ w2, const float* __restrict__ b2,
    const float* __restrict__ w3, const float* __restrict__ b3,
    unsigned int* __restrict__ bias16) {
    extern __shared__ unsigned int smu[];
    const int tid = threadIdx.x, lane = tid & 31, warp = tid >> 5;
    const int r4 = lane >> 2, c4l = lane & 3;

    if (blockIdx.x < NQKV_BLK) {
        // ------------------------- qkv GEMM body --------------------------
        const uint32_t smb = smem_u32(smu);
        const int wm = warp >> 2, wn = warp & 3;
        const int bx = blockIdx.x;
        const int n0 = (bx % 24) * 128, m0 = (bx / 24) * 128;
        const int Kp = 512;
        const int N = P3D;

        float acc[4][4][4];
        #pragma unroll
        for (int i = 0; i < 4; i++)
            #pragma unroll
            for (int j = 0; j < 4; j++)
                #pragma unroll
                for (int q = 0; q < 4; q++) acc[i][j][q] = 0.f;

        auto load_tile = [&](int kp0, int st) {
            const uint32_t sbase = smb + st * QKV_ST * 4;
            #pragma unroll
            for (int t = tid; t < 512; t += 256) {
                int ar = t >> 2, ac = (t & 3) * 4;
                cp16(sbase + (ar * APu + ac) * 4, &A0[(size_t)(m0 + ar) * Kp + kp0 + ac]);
            }
            #pragma unroll
            for (int t = tid; t < 512; t += 256) {
                int br = t >> 5, bc = (t & 31) * 4;
                cp16(sbase + (QKV_SA + br * BPu + bc) * 4,
                     &B0[(size_t)(kp0 + br) * N + n0 + bc]);
            }
            CP_COMMIT();
        };

        load_tile(0, 0);
        for (int it = 0; it < 32; it++) {
            const int st = it & 1;
            CP_WAIT0();
            __syncthreads();
            if (it + 1 < 32) load_tile((it + 1) * 16, st ^ 1);

            const unsigned int* Ah = smu + st * QKV_ST;
            const unsigned int* Bh = smu + st * QKV_ST + QKV_SA;
            #pragma unroll
            for (int ks = 0; ks < 2; ks++) {
                uint32_t ra[4][4], rb[4][2];
                #pragma unroll
                for (int mt = 0; mt < 4; mt++) {
                    const unsigned int* ap =
                        Ah + (wm * 64 + mt * 16 + r4) * APu + 8 * ks + 2 * c4l;
                    uint2 x0 = *(const uint2*)ap;
                    uint2 x1 = *(const uint2*)(ap + 8 * APu);
                    ra[mt][0] = x0.x; ra[mt][1] = x1.x; ra[mt][2] = x0.y; ra[mt][3] = x1.y;
                }
                #pragma unroll
                for (int nt = 0; nt < 4; nt++) {
                    int cn = wn * 32 + nt * 8 + r4;
                    rb[nt][0] = Bh[(8 * ks + c4l) * BPu + cn];
                    rb[nt][1] = Bh[(8 * ks + c4l + 4) * BPu + cn];
                }
                #pragma unroll
                for (int mt = 0; mt < 4; mt++)
                    #pragma unroll
                    for (int nt = 0; nt < 4; nt++)
                        mma16(acc[mt][nt], ra[mt][0], ra[mt][1], ra[mt][2], ra[mt][3],
                              rb[nt][0], rb[nt][1]);
            }
        }

        #pragma unroll
        for (int mt = 0; mt < 4; mt++)
            #pragma unroll
            for (int nt = 0; nt < 4; nt++) {
                int row = m0 + wm * 64 + mt * 16 + r4;
                int col = n0 + wn * 32 + nt * 8 + 2 * c4l;
                float v0 = acc[mt][nt][0], v1 = acc[mt][nt][1];
                float v2 = acc[mt][nt][2], v3 = acc[mt][nt][3];
                if (col < 2 * D) {           // Q,K -> tau-packed half2
                    const float sc = (col < D) ? (0.125f * LOG2E) : 1.0f;
                    const int dd = col & 1023;
                    const int hh = dd >> 6, dh = dd & 63;
                    const int pr = dh >> 1;
                    const int slot = hh * 32 + ((pr & ~7) | tau(pr & 7));
                    unsigned int* dst = (col < D) ? Cq : Ck;
                    dst[(size_t)row * 512 + slot]       = h2pk(v0 * sc, v1 * sc);
                    dst[(size_t)(row + 8) * 512 + slot] = h2pk(v2 * sc, v3 * sc);
                } else {                     // V -> transposed [h][d][kvslot]
                    const int dd = col - 2 * D;
                    const int hh = dd >> 6, dh = dd & 63;
                    const int kp = row >> 1, par = row & 1;
                    const int slot  = (kp & ~7) | tau(kp & 7);
                    const int slot8 = (kp & ~7) | tau((kp & 7) + 4);
                    __half* vb  = Cv + (((size_t)(hh * 64 + dh) << 10) + slot) * 2 + par;
                    __half* vb8 = Cv + (((size_t)(hh * 64 + dh) << 10) + slot8) * 2 + par;
                    vb[0]     = __float2half_rn(v0);
                    vb[2048]  = __float2half_rn(v1);
                    vb8[0]    = __float2half_rn(v2);
                    vb8[2048] = __float2half_rn(v3);
                }
            }
    } else {
        // --------------------------- RPB body ------------------------------
        __shared__ unsigned int h1s[8][16][HPt];

        uint32_t w1b0[4];
        float b1c[4][2], b2c[4][2], w3c[4][2];
        uint32_t w2f[2][4][2];
        #pragma unroll
        for (int nt = 0; nt < 4; nt++) {
            const int n = nt * 8 + r4;
            w1b0[nt] = (c4l == 0) ? h2pk(w1[n], w1[HID + n]) : 0u;
            const int cc = nt * 8 + 2 * c4l;
            b1c[nt][0] = b1[cc]; b1c[nt][1] = b1[cc + 1];
            b2c[nt][0] = b2[cc]; b2c[nt][1] = b2[cc + 1];
            w3c[nt][0] = w3[cc]; w3c[nt][1] = w3[cc + 1];
            #pragma unroll
            for (int ks = 0; ks < 2; ks++) {
                w2f[ks][nt][0] = h2pk(w2[(16 * ks + 2 * c4l) * HID + n],
                                      w2[(16 * ks + 2 * c4l + 1) * HID + n]);
                w2f[ks][nt][1] = h2pk(w2[(16 * ks + 2 * c4l + 8) * HID + n],
                                      w2[(16 * ks + 2 * c4l + 9) * HID + n]);
            }
        }
        const float b3v = b3[0];

        unsigned int (*h1)[HPt] = h1s[warp];
        const int gw = (blockIdx.x - NQKV_BLK) * 8 + warp;
        const int nW = NRPB_BLK * 8;
        for (int task = gw; task < (P * P) / 16; task += nW) {
            const int base = task * 16;
            const float2 ra = *(const float2*)&rel[(size_t)(base + r4) * 2];
            const float2 rb = *(const float2*)&rel[(size_t)(base + 8 + r4) * 2];
            const uint32_t a0 = (c4l == 0) ? h2pk(ra.x, ra.y) : 0u;
            const uint32_t a1 = (c4l == 0) ? h2pk(rb.x, rb.y) : 0u;

            float c1[4][4];
            #pragma unroll
            for (int nt = 0; nt < 4; nt++) {
                c1[nt][0] = b1c[nt][0]; c1[nt][1] = b1c[nt][1];
                c1[nt][2] = b1c[nt][0]; c1[nt][3] = b1c[nt][1];
                mma16(c1[nt], a0, a1, 0u, 0u, w1b0[nt], 0u);
            }
            #pragma unroll
            for (int g = 0; g < 2; g++) {
                uint2 w0 = make_uint2(
                    h2pk(fmaxf(c1[2*g][0], 0.f),   fmaxf(c1[2*g][1], 0.f)),
                    h2pk(fmaxf(c1[2*g+1][0], 0.f), fmaxf(c1[2*g+1][1], 0.f)));
                uint2 w1v = make_uint2(
                    h2pk(fmaxf(c1[2*g][2], 0.f),   fmaxf(c1[2*g][3], 0.f)),
                    h2pk(fmaxf(c1[2*g+1][2], 0.f), fmaxf(c1[2*g+1][3], 0.f)));
                *(uint2*)&h1[r4][8 * g + 2 * c4l]     = w0;
                *(uint2*)&h1[r4 + 8][8 * g + 2 * c4l] = w1v;
            }
            __syncwarp();
            float c2[4][4];
            #pragma unroll
            for (int nt = 0; nt < 4; nt++) {
                c2[nt][0] = b2c[nt][0]; c2[nt][1] = b2c[nt][1];
                c2[nt][2] = b2c[nt][0]; c2[nt][3] = b2c[nt][1];
            }
            #pragma unroll
            for (int ks = 0; ks < 2; ks++) {
                uint2 x0 = *(const uint2*)&h1[r4][8 * ks + 2 * c4l];
                uint2 x1 = *(const uint2*)&h1[r4 + 8][8 * ks + 2 * c4l];
                #pragma unroll
                for (int nt = 0; nt < 4; nt++)
                    mma16(c2[nt], x0.x, x1.x, x0.y, x1.y, w2f[ks][nt][0], w2f[ks][nt][1]);
            }
            float o0 = 0.f, o1 = 0.f;
            #pragma unroll
            for (int nt = 0; nt < 4; nt++) {
                o0 += fmaxf(c2[nt][0], 0.f) * w3c[nt][0] + fmaxf(c2[nt][1], 0.f) * w3c[nt][1];
                o1 += fmaxf(c2[nt][2], 0.f) * w3c[nt][0] + fmaxf(c2[nt][3], 0.f) * w3c[nt][1];
            }
            o0 += __shfl_xor_sync(0xffffffffu, o0, 1);
            o0 += __shfl_xor_sync(0xffffffffu, o0, 2);
            o1 += __shfl_xor_sync(0xffffffffu, o1, 1);
            o1 += __shfl_xor_sync(0xffffffffu, o1, 2);
            float o0n = __shfl_down_sync(0xffffffffu, o0, 4);
            float o1n = __shfl_down_sync(0xffffffffu, o1, 4);
            if (c4l == 0 && !(r4 & 1)) {
                const int pb = base >> 1;
                bias16[pb + (r4 >> 1)]     = h2pk((o0 + b3v) * LOG2E, (o0n + b3v) * LOG2E);
                bias16[pb + 4 + (r4 >> 1)] = h2pk((o1 + b3v) * LOG2E, (o1n + b3v) * LOG2E);
            }
            __syncwarp();
        }
    }
}

// ---------------------------------------------------------------------------
// fp16 proj GEMM (B hi/lo split, 2 MMAs), occupancy 3.
// ---------------------------------------------------------------------------
__global__ __launch_bounds__(128, 3) void gemm_proj(
    const unsigned int* __restrict__ A0,
    const unsigned int* __restrict__ B0, const unsigned int* __restrict__ B1,
    float* __restrict__ C, int M, int N, int K) {
    constexpr int SA = 64 * APu;
    constexpr int SB = 16 * BPu;
    constexpr int BLO = SA + SB;
    constexpr int ST  = SA + 2 * SB;
    extern __shared__ unsigned int smu[];
    const uint32_t smb = smem_u32(smu);

    const int tid = threadIdx.x, lane = tid & 31, warp = tid >> 5;
    const int wn = warp & 3;
    const int m0 = blockIdx.y * 64, n0 = blockIdx.x * 128;
    const int r4 = lane >> 2, c4l = lane & 3;
    const int Kp = K / 2;

    float acc[4][4][4];
    #pragma unroll
    for (int i = 0; i < 4; i++)
        #pragma unroll
        for (int j = 0; j < 4; j++)
            #pragma unroll
            for (int q = 0; q < 4; q++) acc[i][j][q] = 0.f;

    auto load_tile = [&](int kp0, int st) {
        const uint32_t sbase = smb + st * ST * 4;
        #pragma unroll
        for (int t = tid; t < 256; t += 128) {
            int ar = t >> 2, ac = (t & 3) * 4;
            cp16(sbase + (ar * APu + ac) * 4, &A0[(size_t)(m0 + ar) * Kp + kp0 + ac]);
        }
        #pragma unroll
        for (int t = tid; t < 512; t += 128) {
            int br = t >> 5, bc = (t & 31) * 4;
            cp16(sbase + (SA + br * BPu + bc) * 4, &B0[(size_t)(kp0 + br) * N + n0 + bc]);
            cp16(sbase + (BLO + br * BPu + bc) * 4, &B1[(size_t)(kp0 + br) * N + n0 + bc]);
        }
        CP_COMMIT();
    };

    load_tile(0, 0);
    const int niter = K / 32;
    for (int it = 0; it < niter; it++) {
        const int st = it & 1;
        CP_WAIT0();
        __syncthreads();
        if (it + 1 < niter) load_tile((it + 1) * 16, st ^ 1);

        const unsigned int* Ah = smu + st * ST;
        const unsigned int* Bh = smu + st * ST + SA;
        const unsigned int* Bl = smu + st * ST + BLO;
        #pragma unroll
        for (int ks = 0; ks < 2; ks++) {
            uint32_t ra[4][4], rb[4][2], lb[4][2];
            #pragma unroll
            for (int mt = 0; mt < 4; mt++) {
                const unsigned int* ap = Ah + (mt * 16 + r4) * APu + 8 * ks + 2 * c4l;
                uint2 x0 = *(const uint2*)ap;
                uint2 x1 = *(const uint2*)(ap + 8 * APu);
                ra[mt][0] = x0.x; ra[mt][1] = x1.x; ra[mt][2] = x0.y; ra[mt][3] = x1.y;
            }
            #pragma unroll
            for (int nt = 0; nt < 4; nt++) {
                int cn = wn * 32 + nt * 8 + r4;
                rb[nt][0] = Bh[(8 * ks + c4l) * BPu + cn];
                rb[nt][1] = Bh[(8 * ks + c4l + 4) * BPu + cn];
                lb[nt][0] = Bl[(8 * ks + c4l) * BPu + cn];
                lb[nt][1] = Bl[(8 * ks + c4l + 4) * BPu + cn];
            }
            #pragma unroll
            for (int mt = 0; mt < 4; mt++)
                #pragma unroll
                for (int nt = 0; nt < 4; nt++) {
                    mma16(acc[mt][nt], ra[mt][0], ra[mt][1], ra[mt][2], ra[mt][3],
                          rb[nt][0], rb[nt][1]);
                    mma16(acc[mt][nt], ra[mt][0], ra[mt][1], ra[mt][2], ra[mt][3],
                          lb[nt][0], lb[nt][1]);
                }
        }
    }
    #pragma unroll
    for (int mt = 0; mt < 4; mt++)
        #pragma unroll
        for (int nt = 0; nt < 4; nt++) {
            int row = m0 + mt * 16 + r4;
            int col = n0 + wn * 32 + nt * 8 + 2 * c4l;
            *(float2*)&C[(size_t)row * N + col] =
                make_float2(acc[mt][nt][0], acc[mt][nt][1]);
            *(float2*)&C[(size_t)(row + 8) * N + col] =
                make_float2(acc[mt][nt][2], acc[mt][nt][3]);
        }
}

// ---------------------------------------------------------------------------
// Flash attention fp16: P kept in REGISTERS (S-accumulator fragment == PV
// A-fragment after half2 pack) — no P smem round trip, no syncwarp.
// fp16x2 softmax, lp via ones-MMA, fixed origin.
// ---------------------------------------------------------------------------
#define FQ 128
#define FKV 64
#define NIT (P / FKV)
#define OFF_K0 0
#define OFF_K1 2560
#define OFF_V0 5120
#define OFF_V1 7680
#define OFF_P  10240
#define FLASH_SMEM (15360 * 4)
#define ONES2 0x3C003C00u

__global__ __launch_bounds__(256, 2) void flash9(
    const unsigned int* __restrict__ q32, const unsigned int* __restrict__ k32,
    const unsigned int* __restrict__ v32, const unsigned int* __restrict__ bias16,
    unsigned int* __restrict__ ahi) {
    extern __shared__ unsigned int smu[];
    const uint32_t smb = smem_u32(smu);
    const int tid = threadIdx.x, lane = tid & 31, warp = tid >> 5;
    const int r4 = lane >> 2, c4l = lane & 3;
    const int q0 = blockIdx.x * FQ, h = blockIdx.y;
    const int qrow = warp * 16;
    const int grow0 = q0 + qrow + r4, grow1 = grow0 + 8;
    const unsigned int* bp0 = bias16 + ((size_t)grow0 << 10) + c4l;
    const unsigned int* bp1 = bias16 + ((size_t)grow1 << 10) + c4l;

    #pragma unroll
    for (int i = 0; i < 2; i++) {
        int idx = tid + i * 256;
        int r = idx >> 3, seg = (idx & 7) * 4;
        cp16(smb + (OFF_K0 + r * 40 + seg) * 4, &k32[(size_t)r * 512 + h * 32 + seg]);
        cp16(smb + (OFF_V0 + r * 40 + seg) * 4, &v32[(size_t)(h * 64 + r) * 1024 + seg]);
    }
    #pragma unroll
    for (int i = 0; i < 4; i++) {
        int idx = tid + i * 256;
        int row = idx >> 3, seg = (idx & 7) * 4;
        cp16(smb + (OFF_P + row * 40 + seg) * 4, &q32[(size_t)(q0 + row) * 512 + h * 32 + seg]);
    }
    CP_COMMIT();
    CP_WAIT0();
    __syncthreads();

    uint32_t qf[4][4];
    #pragma unroll
    for (int ks = 0; ks < 4; ks++) {
        const unsigned int* qp = smu + OFF_P + (qrow + r4) * 40 + 8 * ks + 2 * c4l;
        uint2 x0 = *(const uint2*)qp;
        uint2 x1 = *(const uint2*)(qp + 8 * 40);
        qf[ks][0] = x0.x; qf[ks][1] = x1.x; qf[ks][2] = x0.y; qf[ks][3] = x1.y;
    }

    float oacc[8][4];
    #pragma unroll
    for (int i = 0; i < 8; i++)
        #pragma unroll
        for (int j = 0; j < 4; j++) oacc[i][j] = 0.f;
    float lacc[4] = {0.f, 0.f, 0.f, 0.f};

    for (int it = 0; it < NIT; it++) {
        const int buf = it & 1;
        const unsigned int* Ks = smu + (buf ? OFF_K1 : OFF_K0);
        const unsigned int* Vs = smu + (buf ? OFF_V1 : OFF_V0);
        CP_WAIT0();
        __syncthreads();

        const int kv0 = it * FKV;
        const int kvp = kv0 >> 1;
        uint32_t bz0[8], bz1[8];
        #pragma unroll
        for (int nt = 0; nt < 8; nt++) {
            bz0[nt] = bp0[kvp + nt * 4];
            bz1[nt] = bp1[kvp + nt * 4];
        }
        if (it + 1 < NIT) {
            const uint32_t ko = buf ? OFF_K0 : OFF_K1;
            const uint32_t vo = buf ? OFF_V0 : OFF_V1;
            #pragma unroll
            for (int i = 0; i < 2; i++) {
                int idx = tid + i * 256;
                int r = idx >> 3, seg = (idx & 7) * 4;
                cp16(smb + (ko + r * 40 + seg) * 4,
                     &k32[(size_t)(kv0 + FKV + r) * 512 + h * 32 + seg]);
                cp16(smb + (vo + r * 40 + seg) * 4,
                     &v32[(size_t)(h * 64 + r) * 1024 + (it + 1) * 32 + seg]);
            }
            CP_COMMIT();
        }

        // S = Q K^T -> fp16x2 softmax -> PV A-fragments IN REGISTERS
        uint32_t pf[4][4];   // pf[g] = {a0, a1, a2, a3} for PV k-chunk g
        #pragma unroll
        for (int g = 0; g < 4; g++) {
            const int ntA = 2 * g, ntB = 2 * g + 1;
            float sA[4] = {0.f, 0.f, 0.f, 0.f}, sB[4] = {0.f, 0.f, 0.f, 0.f};
            #pragma unroll
            for (int ks = 0; ks < 4; ks++) {
                uint2 ka = *(const uint2*)&Ks[(ntA * 8 + r4) * 40 + 8 * ks + 2 * c4l];
                uint2 kb = *(const uint2*)&Ks[(ntB * 8 + r4) * 40 + 8 * ks + 2 * c4l];
                mma16(sA, qf[ks][0], qf[ks][1], qf[ks][2], qf[ks][3], ka.x, ka.y);
                mma16(sB, qf[ks][0], qf[ks][1], qf[ks][2], qf[ks][3], kb.x, kb.y);
            }
            pf[g][0] = ex2h2(hadd2u(h2pk(sA[0], sA[1]), bz0[ntA]));   // a0
            pf[g][1] = ex2h2(hadd2u(h2pk(sA[2], sA[3]), bz1[ntA]));   // a1
            pf[g][2] = ex2h2(hadd2u(h2pk(sB[0], sB[1]), bz0[ntB]));   // a2
            pf[g][3] = ex2h2(hadd2u(h2pk(sB[2], sB[3]), bz1[ntB]));   // a3
        }

        // O += P V  and  lp += P @ ones (P straight from registers)
        #pragma unroll
        for (int g = 0; g < 4; g++) {
            #pragma unroll
            for (int nt = 0; nt < 8; nt++) {
                uint2 vb = *(const uint2*)&Vs[(nt * 8 + r4) * 40 + 8 * g + 2 * c4l];
                mma16(oacc[nt], pf[g][0], pf[g][1], pf[g][2], pf[g][3], vb.x, vb.y);
            }
            mma16(lacc, pf[g][0], pf[g][1], pf[g][2], pf[g][3], ONES2, ONES2);
        }
    }

    const float inv0 = 1.f / lacc[0], inv1 = 1.f / lacc[2];
    #pragma unroll
    for (int nt = 0; nt < 8; nt++) {
        const int slot = h * 32 + 8 * (nt >> 1) + 2 * c4l + (nt & 1);
        ahi[(size_t)(q0 + qrow + r4) * 512 + slot] =
            h2pk(oacc[nt][0] * inv0, oacc[nt][1] * inv0);
        ahi[(size_t)(q0 + qrow + 8 + r4) * 512 + slot] =
            h2pk(oacc[nt][2] * inv1, oacc[nt][3] * inv1);
    }
}

// ---------------------------------------------------------------------------
extern "C" void kernel_launch(void* const* d_in, const int* in_sizes, int n_in,
                              void* d_out, int out_size) {
    const float* x      = (const float*)d_in[0];
    const float* rel    = (const float*)d_in[1];
    const float* w_qkv  = (const float*)d_in[2];
    const float* w_proj = (const float*)d_in[3];
    const float* w1     = (const float*)d_in[4];
    const float* b1     = (const float*)d_in[5];
    const float* w2     = (const float*)d_in[6];
    const float* b2     = (const float*)d_in[7];
    const float* w3     = (const float*)d_in[8];
    const float* b3     = (const float*)d_in[9];
    float* out = (float*)d_out;

    unsigned int *q32, *k32, *v32, *xp, *wqp, *wph, *wpl, *ahi, *bias16;
    cudaGetSymbolAddress((void**)&q32, g_q32);
    cudaGetSymbolAddress((void**)&k32, g_k32);
    cudaGetSymbolAddress((void**)&v32, g_v32);
    cudaGetSymbolAddress((void**)&xp,  g_xp);
    cudaGetSymbolAddress((void**)&wqp, g_wqp);
    cudaGetSymbolAddress((void**)&wph, g_wph);
    cudaGetSymbolAddress((void**)&wpl, g_wpl);
    cudaGetSymbolAddress((void**)&ahi, g_ahi);
    cudaGetSymbolAddress((void**)&bias16, g_bias16);

    constexpr int SM_PROJ = 2 * (64 * APu + 2 * 16 * BPu) * 4;
    cudaFuncSetAttribute(combo_qkv_rpb,
                         cudaFuncAttributeMaxDynamicSharedMemorySize, SM_QKV);
    cudaFuncSetAttribute(gemm_proj,
                         cudaFuncAttributeMaxDynamicSharedMemorySize, SM_PROJ);
    cudaFuncSetAttribute(flash9, cudaFuncAttributeMaxDynamicSharedMemorySize, FLASH_SMEM);

    // 1) fused packs
    pack_all<<<(NPA + NPB + NPC) / 256, 256>>>(x, w_qkv, w_proj, xp, wqp, wph, wpl);
    // 2) qkv GEMM || RPB MLP
    combo_qkv_rpb<<<NQKV_BLK + NRPB_BLK, 256, SM_QKV>>>(
        xp, wqp, q32, k32, (__half*)v32, rel, w1, b1, w2, b2, w3, b3, bias16);
    // 3) flash attention (P in registers)
    flash9<<<dim3(P / FQ, H), 256, FLASH_SMEM>>>(q32, k32, v32, bias16, ahi);
    // 4) proj
    gemm_proj<<<dim3(D / 128, P / 64), 128, SM_PROJ>>>(
        ahi, wph, wpl, out, P, D, D);
}

// round 14
// speedup vs baseline: 1.1409x; 1.0695x over previous
#include <cuda_runtime.h>
#include <cuda_fp16.h>
#include <math.h>
#include <stdint.h>

#define P 2048
#define D 1024
#define H 16
#define DH 64
#define HID 32
#define P3D 3072
#define LOG2E 1.44269504088896f

__device__ unsigned int g_q32[P * 512];        // [P][D/2] tau-packed, q*log2e/8
__device__ unsigned int g_k32[P * 512];        // [P][D/2] tau-packed
__device__ unsigned int g_v32[H * 64 * 1024];  // [H][64 d][1024 kvpair tau-slots]
__device__ unsigned int g_xp[P * 512];         // x tau-packed
__device__ unsigned int g_wqp[512 * P3D];      // w_qkv kpair-packed [D/2][3D]
__device__ unsigned int g_wph[512 * D];        // w_proj hi kpair-packed
__device__ unsigned int g_wpl[512 * D];
__device__ unsigned int g_ahi[P * 512];        // att tau-packed
__device__ unsigned int g_bias16[P * 1024];    // bias*log2e, half2-packed [P][P/2]

__device__ __forceinline__ int tau(int w) { return ((w & 3) << 1) | (w >> 2); }
__device__ __forceinline__ uint32_t h2pk(float a, float b) {
    __half2 h = __floats2half2_rn(a, b);
    return *reinterpret_cast<uint32_t*>(&h);
}
__device__ __forceinline__ uint32_t smem_u32(const void* p) {
    uint32_t a;
    asm("{ .reg .u64 t; cvta.to.shared.u64 t, %1; cvt.u32.u64 %0, t; }" : "=r"(a) : "l"(p));
    return a;
}
__device__ __forceinline__ uint32_t hadd2u(uint32_t a, uint32_t b) {
    uint32_t r; asm("add.f16x2 %0, %1, %2;" : "=r"(r) : "r"(a), "r"(b)); return r;
}
__device__ __forceinline__ uint32_t ex2h2(uint32_t a) {
    uint32_t r; asm("ex2.approx.f16x2 %0, %1;" : "=r"(r) : "r"(a)); return r;
}
__device__ __forceinline__ void mma16(float c[4], uint32_t a0, uint32_t a1,
                                      uint32_t a2, uint32_t a3,
                                      uint32_t b0, uint32_t b1) {
    asm volatile(
        "mma.sync.aligned.m16n8k16.row.col.f32.f16.f16.f32 "
        "{%0,%1,%2,%3},{%4,%5,%6,%7},{%8,%9},{%0,%1,%2,%3};\n"
        : "+f"(c[0]), "+f"(c[1]), "+f"(c[2]), "+f"(c[3])
        : "r"(a0), "r"(a1), "r"(a2), "r"(a3), "r"(b0), "r"(b1));
}
__device__ __forceinline__ void cp16(uint32_t dst, const void* src) {
    asm volatile("cp.async.ca.shared.global [%0], [%1], 16;" :: "r"(dst), "l"(src));
}
#define CP_COMMIT() asm volatile("cp.async.commit_group;" ::: "memory")
#define CP_WAIT0()  asm volatile("cp.async.wait_group 0;" ::: "memory")

// ---------------------------------------------------------------------------
// Single fused pack pre-pass
// ---------------------------------------------------------------------------
#define NPA (P * 512)
#define NPB (512 * P3D)
#define NPC (512 * D)

__global__ void pack_all(const float* __restrict__ x, const float* __restrict__ wq,
                         const float* __restrict__ wp,
                         unsigned int* __restrict__ xp, unsigned int* __restrict__ wqp,
                         unsigned int* __restrict__ wph, unsigned int* __restrict__ wpl) {
    int i = blockIdx.x * blockDim.x + threadIdx.x;
    if (i < NPA) {
        int row = i >> 9, p = i & 511;
        int slot = (p & ~7) | tau(p & 7);
        xp[((size_t)row << 9) + slot] =
            h2pk(x[(size_t)row * 1024 + 2 * p], x[(size_t)row * 1024 + 2 * p + 1]);
    } else if (i < NPA + NPB) {
        int j = i - NPA;
        int kp = j / P3D, n = j % P3D;
        wqp[j] = h2pk(wq[(size_t)(2 * kp) * P3D + n], wq[(size_t)(2 * kp + 1) * P3D + n]);
    } else {
        int j = i - NPA - NPB;
        int kp = j >> 10, n = j & 1023;
        float v0 = wp[(size_t)(2 * kp) * D + n], v1 = wp[(size_t)(2 * kp + 1) * D + n];
        __half h0 = __float2half_rn(v0), h1 = __float2half_rn(v1);
        wph[j] = h2pk(__half2float(h0), __half2float(h1));
        wpl[j] = h2pk(v0 - __half2float(h0), v1 - __half2float(h1));
    }
}

// ---------------------------------------------------------------------------
// Combo kernel: sequential roles (blocks [0,384) qkv, rest rpb).
// ---------------------------------------------------------------------------
#define APu 24
#define BPu 136
#define QKV_SA (128 * APu)
#define QKV_SB (16 * BPu)
#define QKV_ST (QKV_SA + QKV_SB)
#define SM_QKV (2 * QKV_ST * 4)      // 41,984 B
#define NQKV_BLK 384
#define NRPB_BLK 2048
#define HPt 24

__global__ __launch_bounds__(256, 2) void combo_qkv_rpb(
    const unsigned int* __restrict__ A0, const unsigned int* __restrict__ B0,
    unsigned int* __restrict__ Cq, unsigned int* __restrict__ Ck,
    __half* __restrict__ Cv,
    const float* __restrict__ rel,
    const float* __restrict__ w1, const float* __restrict__ b1,
    const float* __restrict__ w2, const float* __restrict__ b2,
    const float* __restrict__ w3, const float* __restrict__ b3,
    unsigned int* __restrict__ bias16) {
    extern __shared__ unsigned int smu[];
    const int tid = threadIdx.x, lane = tid & 31, warp = tid >> 5;
    const int r4 = lane >> 2, c4l = lane & 3;

    if (blockIdx.x < NQKV_BLK) {
        // ------------------------- qkv GEMM body --------------------------
        const uint32_t smb = smem_u32(smu);
        const int wm = warp >> 2, wn = warp & 3;
        const int bx = blockIdx.x;
        const int n0 = (bx % 24) * 128, m0 = (bx / 24) * 128;
        const int Kp = 512;
        const int N = P3D;

        float acc[4][4][4];
        #pragma unroll
        for (int i = 0; i < 4; i++)
            #pragma unroll
            for (int j = 0; j < 4; j++)
                #pragma unroll
                for (int q = 0; q < 4; q++) acc[i][j][q] = 0.f;

        auto load_tile = [&](int kp0, int st) {
            const uint32_t sbase = smb + st * QKV_ST * 4;
            #pragma unroll
            for (int t = tid; t < 512; t += 256) {
                int ar = t >> 2, ac = (t & 3) * 4;
                cp16(sbase + (ar * APu + ac) * 4, &A0[(size_t)(m0 + ar) * Kp + kp0 + ac]);
            }
            #pragma unroll
            for (int t = tid; t < 512; t += 256) {
                int br = t >> 5, bc = (t & 31) * 4;
                cp16(sbase + (QKV_SA + br * BPu + bc) * 4,
                     &B0[(size_t)(kp0 + br) * N + n0 + bc]);
            }
            CP_COMMIT();
        };

        load_tile(0, 0);
        for (int it = 0; it < 32; it++) {
            const int st = it & 1;
            CP_WAIT0();
            __syncthreads();
            if (it + 1 < 32) load_tile((it + 1) * 16, st ^ 1);

            const unsigned int* Ah = smu + st * QKV_ST;
            const unsigned int* Bh = smu + st * QKV_ST + QKV_SA;
            #pragma unroll
            for (int ks = 0; ks < 2; ks++) {
                uint32_t ra[4][4], rb[4][2];
                #pragma unroll
                for (int mt = 0; mt < 4; mt++) {
                    const unsigned int* ap =
                        Ah + (wm * 64 + mt * 16 + r4) * APu + 8 * ks + 2 * c4l;
                    uint2 x0 = *(const uint2*)ap;
                    uint2 x1 = *(const uint2*)(ap + 8 * APu);
                    ra[mt][0] = x0.x; ra[mt][1] = x1.x; ra[mt][2] = x0.y; ra[mt][3] = x1.y;
                }
                #pragma unroll
                for (int nt = 0; nt < 4; nt++) {
                    int cn = wn * 32 + nt * 8 + r4;
                    rb[nt][0] = Bh[(8 * ks + c4l) * BPu + cn];
                    rb[nt][1] = Bh[(8 * ks + c4l + 4) * BPu + cn];
                }
                #pragma unroll
                for (int mt = 0; mt < 4; mt++)
                    #pragma unroll
                    for (int nt = 0; nt < 4; nt++)
                        mma16(acc[mt][nt], ra[mt][0], ra[mt][1], ra[mt][2], ra[mt][3],
                              rb[nt][0], rb[nt][1]);
            }
        }

        #pragma unroll
        for (int mt = 0; mt < 4; mt++)
            #pragma unroll
            for (int nt = 0; nt < 4; nt++) {
                int row = m0 + wm * 64 + mt * 16 + r4;
                int col = n0 + wn * 32 + nt * 8 + 2 * c4l;
                float v0 = acc[mt][nt][0], v1 = acc[mt][nt][1];
                float v2 = acc[mt][nt][2], v3 = acc[mt][nt][3];
                if (col < 2 * D) {           // Q,K -> tau-packed half2
                    const float sc = (col < D) ? (0.125f * LOG2E) : 1.0f;
                    const int dd = col & 1023;
                    const int hh = dd >> 6, dh = dd & 63;
                    const int pr = dh >> 1;
                    const int slot = hh * 32 + ((pr & ~7) | tau(pr & 7));
                    unsigned int* dst = (col < D) ? Cq : Ck;
                    dst[(size_t)row * 512 + slot]       = h2pk(v0 * sc, v1 * sc);
                    dst[(size_t)(row + 8) * 512 + slot] = h2pk(v2 * sc, v3 * sc);
                } else {                     // V -> transposed [h][d][kvslot]
                    const int dd = col - 2 * D;
                    const int hh = dd >> 6, dh = dd & 63;
                    const int kp = row >> 1, par = row & 1;
                    const int slot  = (kp & ~7) | tau(kp & 7);
                    const int slot8 = (kp & ~7) | tau((kp & 7) + 4);
                    __half* vb  = Cv + (((size_t)(hh * 64 + dh) << 10) + slot) * 2 + par;
                    __half* vb8 = Cv + (((size_t)(hh * 64 + dh) << 10) + slot8) * 2 + par;
                    vb[0]     = __float2half_rn(v0);
                    vb[2048]  = __float2half_rn(v1);
                    vb8[0]    = __float2half_rn(v2);
                    vb8[2048] = __float2half_rn(v3);
                }
            }
    } else {
        // --------------------------- RPB body ------------------------------
        __shared__ unsigned int h1s[8][16][HPt];

        uint32_t w1b0[4];
        float b1c[4][2], b2c[4][2], w3c[4][2];
        uint32_t w2f[2][4][2];
        #pragma unroll
        for (int nt = 0; nt < 4; nt++) {
            const int n = nt * 8 + r4;
            w1b0[nt] = (c4l == 0) ? h2pk(w1[n], w1[HID + n]) : 0u;
            const int cc = nt * 8 + 2 * c4l;
            b1c[nt][0] = b1[cc]; b1c[nt][1] = b1[cc + 1];
            b2c[nt][0] = b2[cc]; b2c[nt][1] = b2[cc + 1];
            w3c[nt][0] = w3[cc]; w3c[nt][1] = w3[cc + 1];
            #pragma unroll
            for (int ks = 0; ks < 2; ks++) {
                w2f[ks][nt][0] = h2pk(w2[(16 * ks + 2 * c4l) * HID + n],
                                      w2[(16 * ks + 2 * c4l + 1) * HID + n]);
                w2f[ks][nt][1] = h2pk(w2[(16 * ks + 2 * c4l + 8) * HID + n],
                                      w2[(16 * ks + 2 * c4l + 9) * HID + n]);
            }
        }
        const float b3v = b3[0];

        unsigned int (*h1)[HPt] = h1s[warp];
        const int gw = (blockIdx.x - NQKV_BLK) * 8 + warp;
        const int nW = NRPB_BLK * 8;
        for (int task = gw; task < (P * P) / 16; task += nW) {
            const int base = task * 16;
            const float2 ra = *(const float2*)&rel[(size_t)(base + r4) * 2];
            const float2 rb = *(const float2*)&rel[(size_t)(base + 8 + r4) * 2];
            const uint32_t a0 = (c4l == 0) ? h2pk(ra.x, ra.y) : 0u;
            const uint32_t a1 = (c4l == 0) ? h2pk(rb.x, rb.y) : 0u;

            float c1[4][4];
            #pragma unroll
            for (int nt = 0; nt < 4; nt++) {
                c1[nt][0] = b1c[nt][0]; c1[nt][1] = b1c[nt][1];
                c1[nt][2] = b1c[nt][0]; c1[nt][3] = b1c[nt][1];
                mma16(c1[nt], a0, a1, 0u, 0u, w1b0[nt], 0u);
            }
            #pragma unroll
            for (int g = 0; g < 2; g++) {
                uint2 w0 = make_uint2(
                    h2pk(fmaxf(c1[2*g][0], 0.f),   fmaxf(c1[2*g][1], 0.f)),
                    h2pk(fmaxf(c1[2*g+1][0], 0.f), fmaxf(c1[2*g+1][1], 0.f)));
                uint2 w1v = make_uint2(
                    h2pk(fmaxf(c1[2*g][2], 0.f),   fmaxf(c1[2*g][3], 0.f)),
                    h2pk(fmaxf(c1[2*g+1][2], 0.f), fmaxf(c1[2*g+1][3], 0.f)));
                *(uint2*)&h1[r4][8 * g + 2 * c4l]     = w0;
                *(uint2*)&h1[r4 + 8][8 * g + 2 * c4l] = w1v;
            }
            __syncwarp();
            float c2[4][4];
            #pragma unroll
            for (int nt = 0; nt < 4; nt++) {
                c2[nt][0] = b2c[nt][0]; c2[nt][1] = b2c[nt][1];
                c2[nt][2] = b2c[nt][0]; c2[nt][3] = b2c[nt][1];
            }
            #pragma unroll
            for (int ks = 0; ks < 2; ks++) {
                uint2 x0 = *(const uint2*)&h1[r4][8 * ks + 2 * c4l];
                uint2 x1 = *(const uint2*)&h1[r4 + 8][8 * ks + 2 * c4l];
                #pragma unroll
                for (int nt = 0; nt < 4; nt++)
                    mma16(c2[nt], x0.x, x1.x, x0.y, x1.y, w2f[ks][nt][0], w2f[ks][nt][1]);
            }
            float o0 = 0.f, o1 = 0.f;
            #pragma unroll
            for (int nt = 0; nt < 4; nt++) {
                o0 += fmaxf(c2[nt][0], 0.f) * w3c[nt][0] + fmaxf(c2[nt][1], 0.f) * w3c[nt][1];
                o1 += fmaxf(c2[nt][2], 0.f) * w3c[nt][0] + fmaxf(c2[nt][3], 0.f) * w3c[nt][1];
            }
            o0 += __shfl_xor_sync(0xffffffffu, o0, 1);
            o0 += __shfl_xor_sync(0xffffffffu, o0, 2);
            o1 += __shfl_xor_sync(0xffffffffu, o1, 1);
            o1 += __shfl_xor_sync(0xffffffffu, o1, 2);
            float o0n = __shfl_down_sync(0xffffffffu, o0, 4);
            float o1n = __shfl_down_sync(0xffffffffu, o1, 4);
            if (c4l == 0 && !(r4 & 1)) {
                const int pb = base >> 1;
                bias16[pb + (r4 >> 1)]     = h2pk((o0 + b3v) * LOG2E, (o0n + b3v) * LOG2E);
                bias16[pb + 4 + (r4 >> 1)] = h2pk((o1 + b3v) * LOG2E, (o1n + b3v) * LOG2E);
            }
            __syncwarp();
        }
    }
}

// ---------------------------------------------------------------------------
// fp16 proj GEMM (B hi/lo split, 2 MMAs).
// ---------------------------------------------------------------------------
__global__ __launch_bounds__(128, 3) void gemm_proj(
    const unsigned int* __restrict__ A0,
    const unsigned int* __restrict__ B0, const unsigned int* __restrict__ B1,
    float* __restrict__ C, int M, int N, int K) {
    constexpr int SA = 64 * APu;
    constexpr int SB = 16 * BPu;
    constexpr int BLO = SA + SB;
    constexpr int ST  = SA + 2 * SB;
    extern __shared__ unsigned int smu[];
    const uint32_t smb = smem_u32(smu);

    const int tid = threadIdx.x, lane = tid & 31, warp = tid >> 5;
    const int wn = warp & 3;
    const int m0 = blockIdx.y * 64, n0 = blockIdx.x * 128;
    const int r4 = lane >> 2, c4l = lane & 3;
    const int Kp = K / 2;

    float acc[4][4][4];
    #pragma unroll
    for (int i = 0; i < 4; i++)
        #pragma unroll
        for (int j = 0; j < 4; j++)
            #pragma unroll
            for (int q = 0; q < 4; q++) acc[i][j][q] = 0.f;

    auto load_tile = [&](int kp0, int st) {
        const uint32_t sbase = smb + st * ST * 4;
        #pragma unroll
        for (int t = tid; t < 256; t += 128) {
            int ar = t >> 2, ac = (t & 3) * 4;
            cp16(sbase + (ar * APu + ac) * 4, &A0[(size_t)(m0 + ar) * Kp + kp0 + ac]);
        }
        #pragma unroll
        for (int t = tid; t < 512; t += 128) {
            int br = t >> 5, bc = (t & 31) * 4;
            cp16(sbase + (SA + br * BPu + bc) * 4, &B0[(size_t)(kp0 + br) * N + n0 + bc]);
            cp16(sbase + (BLO + br * BPu + bc) * 4, &B1[(size_t)(kp0 + br) * N + n0 + bc]);
        }
        CP_COMMIT();
    };

    load_tile(0, 0);
    const int niter = K / 32;
    for (int it = 0; it < niter; it++) {
        const int st = it & 1;
        CP_WAIT0();
        __syncthreads();
        if (it + 1 < niter) load_tile((it + 1) * 16, st ^ 1);

        const unsigned int* Ah = smu + st * ST;
        const unsigned int* Bh = smu + st * ST + SA;
        const unsigned int* Bl = smu + st * ST + BLO;
        #pragma unroll
        for (int ks = 0; ks < 2; ks++) {
            uint32_t ra[4][4], rb[4][2], lb[4][2];
            #pragma unroll
            for (int mt = 0; mt < 4; mt++) {
                const unsigned int* ap = Ah + (mt * 16 + r4) * APu + 8 * ks + 2 * c4l;
                uint2 x0 = *(const uint2*)ap;
                uint2 x1 = *(const uint2*)(ap + 8 * APu);
                ra[mt][0] = x0.x; ra[mt][1] = x1.x; ra[mt][2] = x0.y; ra[mt][3] = x1.y;
            }
            #pragma unroll
            for (int nt = 0; nt < 4; nt++) {
                int cn = wn * 32 + nt * 8 + r4;
                rb[nt][0] = Bh[(8 * ks + c4l) * BPu + cn];
                rb[nt][1] = Bh[(8 * ks + c4l + 4) * BPu + cn];
                lb[nt][0] = Bl[(8 * ks + c4l) * BPu + cn];
                lb[nt][1] = Bl[(8 * ks + c4l + 4) * BPu + cn];
            }
            #pragma unroll
            for (int mt = 0; mt < 4; mt++)
                #pragma unroll
                for (int nt = 0; nt < 4; nt++) {
                    mma16(acc[mt][nt], ra[mt][0], ra[mt][1], ra[mt][2], ra[mt][3],
                          rb[nt][0], rb[nt][1]);
                    mma16(acc[mt][nt], ra[mt][0], ra[mt][1], ra[mt][2], ra[mt][3],
                          lb[nt][0], lb[nt][1]);
                }
        }
    }
    #pragma unroll
    for (int mt = 0; mt < 4; mt++)
        #pragma unroll
        for (int nt = 0; nt < 4; nt++) {
            int row = m0 + mt * 16 + r4;
            int col = n0 + wn * 32 + nt * 8 + 2 * c4l;
            *(float2*)&C[(size_t)row * N + col] =
                make_float2(acc[mt][nt][0], acc[mt][nt][1]);
            *(float2*)&C[(size_t)(row + 8) * N + col] =
                make_float2(acc[mt][nt][2], acc[mt][nt][3]);
        }
}

// ---------------------------------------------------------------------------
// Flash attention fp16: K/V AND BIAS all cp.async double-buffered one tile
// ahead; P in registers; fp16x2 softmax; lp via ones-MMA; fixed origin.
// Bias smem pitch 36 -> banks (4*r4 + c4l + const), conflict-free.
// ---------------------------------------------------------------------------
#define FQ 128
#define FKV 64
#define NIT (P / FKV)
#define OFF_K0 0
#define OFF_K1 2560
#define OFF_V0 5120
#define OFF_V1 7680
#define OFF_B0 10240
#define OFF_B1 14848
#define BPit 36
#define FLASH_SMEM (19456 * 4)   // 77,824 B
#define ONES2 0x3C003C00u

__global__ __launch_bounds__(256, 2) void flash10(
    const unsigned int* __restrict__ q32, const unsigned int* __restrict__ k32,
    const unsigned int* __restrict__ v32, const unsigned int* __restrict__ bias16,
    unsigned int* __restrict__ ahi) {
    extern __shared__ unsigned int smu[];
    const uint32_t smb = smem_u32(smu);
    const int tid = threadIdx.x, lane = tid & 31, warp = tid >> 5;
    const int r4 = lane >> 2, c4l = lane & 3;
    const int q0 = blockIdx.x * FQ, h = blockIdx.y;
    const int qrow = warp * 16;

    // K/V tile 0 (async, group 1)
    #pragma unroll
    for (int i = 0; i < 2; i++) {
        int idx = tid + i * 256;
        int r = idx >> 3, seg = (idx & 7) * 4;
        cp16(smb + (OFF_K0 + r * 40 + seg) * 4, &k32[(size_t)r * 512 + h * 32 + seg]);
        cp16(smb + (OFF_V0 + r * 40 + seg) * 4, &v32[(size_t)(h * 64 + r) * 1024 + seg]);
    }
    CP_COMMIT();

    // Stage Q through the (not yet used) bias region, pitch 40
    #pragma unroll
    for (int i = 0; i < 4; i++) {
        int idx = tid + i * 256;
        int row = idx >> 3, seg = (idx & 7) * 4;
        *(uint4*)&smu[OFF_B0 + row * 40 + seg] =
            *(const uint4*)&q32[(size_t)(q0 + row) * 512 + h * 32 + seg];
    }
    __syncthreads();
    uint32_t qf[4][4];
    #pragma unroll
    for (int ks = 0; ks < 4; ks++) {
        const unsigned int* qp = smu + OFF_B0 + (qrow + r4) * 40 + 8 * ks + 2 * c4l;
        uint2 x0 = *(const uint2*)qp;
        uint2 x1 = *(const uint2*)(qp + 8 * 40);
        qf[ks][0] = x0.x; qf[ks][1] = x1.x; qf[ks][2] = x0.y; qf[ks][3] = x1.y;
    }
    __syncthreads();   // all Q reads done before bias tile 0 overwrites the region

    // bias tile 0 (async, group 2)
    #pragma unroll
    for (int i = 0; i < 4; i++) {
        int idx = tid + i * 256;
        int r = idx >> 3, ch = (idx & 7) * 4;
        cp16(smb + (OFF_B0 + r * BPit + ch) * 4,
             &bias16[((size_t)(q0 + r) << 10) + ch]);
    }
    CP_COMMIT();

    float oacc[8][4];
    #pragma unroll
    for (int i = 0; i < 8; i++)
        #pragma unroll
        for (int j = 0; j < 4; j++) oacc[i][j] = 0.f;
    float lacc[4] = {0.f, 0.f, 0.f, 0.f};

    for (int it = 0; it < NIT; it++) {
        const int buf = it & 1;
        const unsigned int* Ks = smu + (buf ? OFF_K1 : OFF_K0);
        const unsigned int* Vs = smu + (buf ? OFF_V1 : OFF_V0);
        const unsigned int* Bs = smu + (buf ? OFF_B1 : OFF_B0);
        CP_WAIT0();
        __syncthreads();

        if (it + 1 < NIT) {
            const int kv1 = (it + 1) * FKV;
            const uint32_t ko = buf ? OFF_K0 : OFF_K1;
            const uint32_t vo = buf ? OFF_V0 : OFF_V1;
            const uint32_t bo = buf ? OFF_B0 : OFF_B1;
            #pragma unroll
            for (int i = 0; i < 2; i++) {
                int idx = tid + i * 256;
                int r = idx >> 3, seg = (idx & 7) * 4;
                cp16(smb + (ko + r * 40 + seg) * 4,
                     &k32[(size_t)(kv1 + r) * 512 + h * 32 + seg]);
                cp16(smb + (vo + r * 40 + seg) * 4,
                     &v32[(size_t)(h * 64 + r) * 1024 + (it + 1) * 32 + seg]);
            }
            #pragma unroll
            for (int i = 0; i < 4; i++) {
                int idx = tid + i * 256;
                int r = idx >> 3, ch = (idx & 7) * 4;
                cp16(smb + (bo + r * BPit + ch) * 4,
                     &bias16[((size_t)(q0 + r) << 10) + (it + 1) * 32 + ch]);
            }
            CP_COMMIT();
        }

        // S = Q K^T -> fp16x2 softmax (bias from smem) -> PV A-frags in regs
        uint32_t pf[4][4];
        #pragma unroll
        for (int g = 0; g < 4; g++) {
            const int ntA = 2 * g, ntB = 2 * g + 1;
            float sA[4] = {0.f, 0.f, 0.f, 0.f}, sB[4] = {0.f, 0.f, 0.f, 0.f};
            #pragma unroll
            for (int ks = 0; ks < 4; ks++) {
                uint2 ka = *(const uint2*)&Ks[(ntA * 8 + r4) * 40 + 8 * ks + 2 * c4l];
                uint2 kb = *(const uint2*)&Ks[(ntB * 8 + r4) * 40 + 8 * ks + 2 * c4l];
                mma16(sA, qf[ks][0], qf[ks][1], qf[ks][2], qf[ks][3], ka.x, ka.y);
                mma16(sB, qf[ks][0], qf[ks][1], qf[ks][2], qf[ks][3], kb.x, kb.y);
            }
            const uint32_t bA0 = Bs[(qrow + r4) * BPit + ntA * 4 + c4l];
            const uint32_t bA1 = Bs[(qrow + 8 + r4) * BPit + ntA * 4 + c4l];
            const uint32_t bB0 = Bs[(qrow + r4) * BPit + ntB * 4 + c4l];
            const uint32_t bB1 = Bs[(qrow + 8 + r4) * BPit + ntB * 4 + c4l];
            pf[g][0] = ex2h2(hadd2u(h2pk(sA[0], sA[1]), bA0));
            pf[g][1] = ex2h2(hadd2u(h2pk(sA[2], sA[3]), bA1));
            pf[g][2] = ex2h2(hadd2u(h2pk(sB[0], sB[1]), bB0));
            pf[g][3] = ex2h2(hadd2u(h2pk(sB[2], sB[3]), bB1));
        }

        // O += P V  and  lp += P @ ones
        #pragma unroll
        for (int g = 0; g < 4; g++) {
            #pragma unroll
            for (int nt = 0; nt < 8; nt++) {
                uint2 vb = *(const uint2*)&Vs[(nt * 8 + r4) * 40 + 8 * g + 2 * c4l];
                mma16(oacc[nt], pf[g][0], pf[g][1], pf[g][2], pf[g][3], vb.x, vb.y);
            }
            mma16(lacc, pf[g][0], pf[g][1], pf[g][2], pf[g][3], ONES2, ONES2);
        }
    }

    const float inv0 = 1.f / lacc[0], inv1 = 1.f / lacc[2];
    #pragma unroll
    for (int nt = 0; nt < 8; nt++) {
        const int slot = h * 32 + 8 * (nt >> 1) + 2 * c4l + (nt & 1);
        ahi[(size_t)(q0 + qrow + r4) * 512 + slot] =
            h2pk(oacc[nt][0] * inv0, oacc[nt][1] * inv0);
        ahi[(size_t)(q0 + qrow + 8 + r4) * 512 + slot] =
            h2pk(oacc[nt][2] * inv1, oacc[nt][3] * inv1);
    }
}

// ---------------------------------------------------------------------------
extern "C" void kernel_launch(void* const* d_in, const int* in_sizes, int n_in,
                              void* d_out, int out_size) {
    const float* x      = (const float*)d_in[0];
    const float* rel    = (const float*)d_in[1];
    const float* w_qkv  = (const float*)d_in[2];
    const float* w_proj = (const float*)d_in[3];
    const float* w1     = (const float*)d_in[4];
    const float* b1     = (const float*)d_in[5];
    const float* w2     = (const float*)d_in[6];
    const float* b2     = (const float*)d_in[7];
    const float* w3     = (const float*)d_in[8];
    const float* b3     = (const float*)d_in[9];
    float* out = (float*)d_out;

    unsigned int *q32, *k32, *v32, *xp, *wqp, *wph, *wpl, *ahi, *bias16;
    cudaGetSymbolAddress((void**)&q32, g_q32);
    cudaGetSymbolAddress((void**)&k32, g_k32);
    cudaGetSymbolAddress((void**)&v32, g_v32);
    cudaGetSymbolAddress((void**)&xp,  g_xp);
    cudaGetSymbolAddress((void**)&wqp, g_wqp);
    cudaGetSymbolAddress((void**)&wph, g_wph);
    cudaGetSymbolAddress((void**)&wpl, g_wpl);
    cudaGetSymbolAddress((void**)&ahi, g_ahi);
    cudaGetSymbolAddress((void**)&bias16, g_bias16);

    constexpr int SM_PROJ = 2 * (64 * APu + 2 * 16 * BPu) * 4;
    cudaFuncSetAttribute(combo_qkv_rpb,
                         cudaFuncAttributeMaxDynamicSharedMemorySize, SM_QKV);
    cudaFuncSetAttribute(gemm_proj,
                         cudaFuncAttributeMaxDynamicSharedMemorySize, SM_PROJ);
    cudaFuncSetAttribute(flash10, cudaFuncAttributeMaxDynamicSharedMemorySize, FLASH_SMEM);

    // 1) fused packs
    pack_all<<<(NPA + NPB + NPC) / 256, 256>>>(x, w_qkv, w_proj, xp, wqp, wph, wpl);
    // 2) qkv GEMM || RPB MLP
    combo_qkv_rpb<<<NQKV_BLK + NRPB_BLK, 256, SM_QKV>>>(
        xp, wqp, q32, k32, (__half*)v32, rel, w1, b1, w2, b2, w3, b3, bias16);
    // 3) flash attention (bias cp.async-pipelined)
    flash10<<<dim3(P / FQ, H), 256, FLASH_SMEM>>>(q32, k32, v32, bias16, ahi);
    // 4) proj
    gemm_proj<<<dim3(D / 128, P / 64), 128, SM_PROJ>>>(
        ahi, wph, wpl, out, P, D, D);
}